// round 8
// baseline (speedup 1.0000x reference)
#include <cuda_runtime.h>
#include <cuda_bf16.h>
#include <math.h>
#include <stdint.h>

#define SQ 2048
#define NH 16
#define QRR 1536
#define KRR 512
#define TOPK 512
#define DMM 2048
#define NEG_INF (__int_as_float(0xff800000))
typedef __nv_bfloat16 bf16;

// ---------------- fp32 scratch ----------------
__device__ float g_qr[SQ*QRR];
__device__ float g_q[SQ*NH*192];
__device__ float g_kvall[SQ*576];
__device__ float g_kv[SQ*KRR];
__device__ float g_kvp[SQ*NH*256];
__device__ float g_k[SQ*NH*192];
__device__ float g_qi[SQ*32*128];
__device__ float g_ki[SQ*128];
__device__ float g_wts[SQ*32];
__device__ float g_iscore[SQ*SQ];
__device__ float g_comb[SQ*SQ];
__device__ float g_scores[67108864];
__device__ float g_attnout[SQ*DMM];
// ---------------- bf16 hi/lo scratch (smooth path only) ----------------
__device__ bf16 g_h_hi[2048*2048],  g_h_lo[2048*2048];
__device__ bf16 g_wqb_hi[3072*1536],g_wqb_lo[3072*1536];
__device__ bf16 g_wkva_hi[576*2048],g_wkva_lo[576*2048];
__device__ bf16 g_wkvb_hi[4096*512],g_wkvb_lo[4096*512];
__device__ bf16 g_wo_hi[2048*2048], g_wo_lo[2048*2048];
__device__ bf16 g_qrn_hi[2048*1536],g_qrn_lo[2048*1536];
__device__ bf16 g_kvn_hi[2048*512], g_kvn_lo[2048*512];
__device__ bf16 g_qh_hi[2048*3072], g_qh_lo[2048*3072];
__device__ bf16 g_kh_hi[2048*3072], g_kh_lo[2048*3072];
__device__ bf16 g_at_hi[2048*2048], g_at_lo[2048*2048];
__device__ bf16 g_p_hi[67108864],   g_p_lo[67108864];
__device__ bf16 g_vT_hi[16*128*2048], g_vT_lo[16*128*2048];

// ================= mma.sync helpers =================
__device__ __forceinline__ uint32_t smem_u32(const void* p){
    uint32_t a; asm("{ .reg .u64 t; cvta.to.shared.u64 t, %1; cvt.u32.u64 %0, t; }":"=r"(a):"l"(p)); return a;
}
#define LDSM4(R, ADDR) asm volatile( \
    "ldmatrix.sync.aligned.m8n8.x4.shared.b16 {%0,%1,%2,%3}, [%4];" \
    : "=r"((R)[0]),"=r"((R)[1]),"=r"((R)[2]),"=r"((R)[3]) : "r"(ADDR))
#define MMA16816(D, A, B) asm volatile( \
    "mma.sync.aligned.m16n8k16.row.col.f32.bf16.bf16.f32 " \
    "{%0,%1,%2,%3}, {%4,%5,%6,%7}, {%8,%9}, {%0,%1,%2,%3};" \
    : "+f"((D)[0]),"+f"((D)[1]),"+f"((D)[2]),"+f"((D)[3]) \
    : "r"((A)[0]),"r"((A)[1]),"r"((A)[2]),"r"((A)[3]), "r"((B)[0]),"r"((B)[1]))

// ======= bf16x3 NT GEMM via mma.sync (smooth path) =======
// causal: 0=dense, 1=skip above-diagonal tiles, 2=K capped at m0+128 (PV)
#define LSTR 72
#define MMA_SMEM (4*128*LSTR*2)
__global__ __launch_bounds__(256) void gemm_mma_nt(
    const bf16* __restrict__ Ah, const bf16* __restrict__ Al, long sa, int lda,
    const bf16* __restrict__ Bh, const bf16* __restrict__ Bl, long sb, int ldb,
    float* __restrict__ C, long sc, int ldc, int N, int K, float alpha, int causal)
{
    int n0 = blockIdx.x*128, m0 = blockIdx.y*128;
    if (causal == 1 && n0 > m0+127) return;
    int Keff = K;
    if (causal == 2 && m0+128 < Keff) Keff = m0+128;
    Ah += (long)blockIdx.z*sa; Al += (long)blockIdx.z*sa;
    Bh += (long)blockIdx.z*sb; Bl += (long)blockIdx.z*sb;
    C  += (long)blockIdx.z*sc;

    extern __shared__ bf16 sm[];
    bf16 *sAh = sm, *sAl = sm + 128*LSTR, *sBh = sm + 2*128*LSTR, *sBl = sm + 3*128*LSTR;
    int tid = threadIdx.x, lane = tid & 31, wid = tid >> 5;
    int wm = (wid >> 1) * 32, wn = (wid & 1) * 64;
    float acc[2][8][4] = {};

    for (int kc = 0; kc < Keff; kc += 64){
        __syncthreads();
        #pragma unroll
        for (int it = 0; it < 4; it++){
            int c = tid + it*256, row = c >> 3, cb = (c & 7) * 8;
            long ga = (long)(m0+row)*lda + kc + cb;
            *(int4*)&sAh[row*LSTR + cb] = *(const int4*)(Ah + ga);
            *(int4*)&sAl[row*LSTR + cb] = *(const int4*)(Al + ga);
            int4 vh = make_int4(0,0,0,0), vl = vh;
            if (n0 + row < N){
                long gb = (long)(n0+row)*ldb + kc + cb;
                vh = *(const int4*)(Bh + gb); vl = *(const int4*)(Bl + gb);
            }
            *(int4*)&sBh[row*LSTR + cb] = vh;
            *(int4*)&sBl[row*LSTR + cb] = vl;
        }
        __syncthreads();

        int r = lane & 15, ko = (lane >> 4) * 8;
        #pragma unroll
        for (int ks = 0; ks < 4; ks++){
            uint32_t ah[2][4], al[2][4], bh[8][2], bl[8][2];
            #pragma unroll
            for (int mi = 0; mi < 2; mi++){
                uint32_t ad = smem_u32(&sAh[(wm + mi*16 + r)*LSTR + ks*16 + ko]);
                LDSM4(ah[mi], ad);
                ad = smem_u32(&sAl[(wm + mi*16 + r)*LSTR + ks*16 + ko]);
                LDSM4(al[mi], ad);
            }
            #pragma unroll
            for (int np = 0; np < 4; np++){
                uint32_t t4[4];
                uint32_t bd = smem_u32(&sBh[(wn + np*16 + r)*LSTR + ks*16 + ko]);
                LDSM4(t4, bd);
                bh[2*np][0]=t4[0]; bh[2*np][1]=t4[2]; bh[2*np+1][0]=t4[1]; bh[2*np+1][1]=t4[3];
                bd = smem_u32(&sBl[(wn + np*16 + r)*LSTR + ks*16 + ko]);
                LDSM4(t4, bd);
                bl[2*np][0]=t4[0]; bl[2*np][1]=t4[2]; bl[2*np+1][0]=t4[1]; bl[2*np+1][1]=t4[3];
            }
            #pragma unroll
            for (int mi = 0; mi < 2; mi++)
                #pragma unroll
                for (int ni = 0; ni < 8; ni++){
                    MMA16816(acc[mi][ni], ah[mi], bh[ni]);
                    MMA16816(acc[mi][ni], ah[mi], bl[ni]);
                    MMA16816(acc[mi][ni], al[mi], bh[ni]);
                }
        }
    }
    #pragma unroll
    for (int mi = 0; mi < 2; mi++){
        int mrow = m0 + wm + mi*16 + (lane >> 2);
        #pragma unroll
        for (int ni = 0; ni < 8; ni++){
            int n = n0 + wn + ni*8 + (lane & 3)*2;
            if (n < N){
                *(float2*)(C + (long)mrow*ldc + n)     = make_float2(alpha*acc[mi][ni][0], alpha*acc[mi][ni][1]);
                *(float2*)(C + (long)(mrow+8)*ldc + n) = make_float2(alpha*acc[mi][ni][2], alpha*acc[mi][ni][3]);
            }
        }
    }
}

// ======= fp32 SIMT NT GEMM 128x128 (bit-identical baseline) =======
__global__ __launch_bounds__(256) void gemm_nt_k(
    const float* __restrict__ A, long sa, int lda,
    const float* __restrict__ B, long sb, int ldb,
    float* __restrict__ C, long sc, int ldc,
    int M, int N, int K, float alpha, int causal)
{
    A += (long)blockIdx.z*sa; B += (long)blockIdx.z*sb; C += (long)blockIdx.z*sc;
    int n0 = blockIdx.x*128, m0 = blockIdx.y*128;
    if (causal && n0 > m0+127) return;
    __shared__ float As[2][16][128];
    __shared__ float Bs[2][16][128];
    int tx = threadIdx.x, ty = threadIdx.y, tid = ty*16+tx;
    int lrow = tid>>1, lcol = (tid&1)*8;
    const float* Ap = A + (long)(m0+lrow)*lda + lcol;
    const float* Bp = B + (long)(n0+lrow)*ldb + lcol;
    bool aval = (m0+lrow) < M, bval = (n0+lrow) < N;
    float4 ra0, ra1, rb0, rb1;
    const float4 z4 = make_float4(0.f,0.f,0.f,0.f);
    ra0 = aval ? *(const float4*)(Ap)   : z4;
    ra1 = aval ? *(const float4*)(Ap+4) : z4;
    rb0 = bval ? *(const float4*)(Bp)   : z4;
    rb1 = bval ? *(const float4*)(Bp+4) : z4;
    As[0][lcol+0][lrow]=ra0.x; As[0][lcol+1][lrow]=ra0.y; As[0][lcol+2][lrow]=ra0.z; As[0][lcol+3][lrow]=ra0.w;
    As[0][lcol+4][lrow]=ra1.x; As[0][lcol+5][lrow]=ra1.y; As[0][lcol+6][lrow]=ra1.z; As[0][lcol+7][lrow]=ra1.w;
    Bs[0][lcol+0][lrow]=rb0.x; Bs[0][lcol+1][lrow]=rb0.y; Bs[0][lcol+2][lrow]=rb0.z; Bs[0][lcol+3][lrow]=rb0.w;
    Bs[0][lcol+4][lrow]=rb1.x; Bs[0][lcol+5][lrow]=rb1.y; Bs[0][lcol+6][lrow]=rb1.z; Bs[0][lcol+7][lrow]=rb1.w;
    __syncthreads();
    float acc[8][8] = {};
    int nk = K>>4;
    for (int kt=0; kt<nk; kt++){
        int cur = kt&1;
        if (kt+1<nk){
            const float* Ap2 = Ap + (kt+1)*16;
            const float* Bp2 = Bp + (kt+1)*16;
            ra0 = aval ? *(const float4*)(Ap2)   : z4;
            ra1 = aval ? *(const float4*)(Ap2+4) : z4;
            rb0 = bval ? *(const float4*)(Bp2)   : z4;
            rb1 = bval ? *(const float4*)(Bp2+4) : z4;
        }
        #pragma unroll
        for (int k=0;k<16;k++){
            float4 a0=*(const float4*)(&As[cur][k][ty*8]);
            float4 a1=*(const float4*)(&As[cur][k][ty*8+4]);
            float4 b0=*(const float4*)(&Bs[cur][k][tx*8]);
            float4 b1=*(const float4*)(&Bs[cur][k][tx*8+4]);
            float a[8]={a0.x,a0.y,a0.z,a0.w,a1.x,a1.y,a1.z,a1.w};
            float b[8]={b0.x,b0.y,b0.z,b0.w,b1.x,b1.y,b1.z,b1.w};
            #pragma unroll
            for (int i=0;i<8;i++)
                #pragma unroll
                for (int j=0;j<8;j++) acc[i][j]+=a[i]*b[j];
        }
        if (kt+1<nk){
            int nx = cur^1;
            As[nx][lcol+0][lrow]=ra0.x; As[nx][lcol+1][lrow]=ra0.y; As[nx][lcol+2][lrow]=ra0.z; As[nx][lcol+3][lrow]=ra0.w;
            As[nx][lcol+4][lrow]=ra1.x; As[nx][lcol+5][lrow]=ra1.y; As[nx][lcol+6][lrow]=ra1.z; As[nx][lcol+7][lrow]=ra1.w;
            Bs[nx][lcol+0][lrow]=rb0.x; Bs[nx][lcol+1][lrow]=rb0.y; Bs[nx][lcol+2][lrow]=rb0.z; Bs[nx][lcol+3][lrow]=rb0.w;
            Bs[nx][lcol+4][lrow]=rb1.x; Bs[nx][lcol+5][lrow]=rb1.y; Bs[nx][lcol+6][lrow]=rb1.z; Bs[nx][lcol+7][lrow]=rb1.w;
        }
        __syncthreads();
    }
    #pragma unroll
    for (int i=0;i<8;i++){
        int m = m0+ty*8+i;
        if (m >= M) continue;
        int n = n0+tx*8;
        if (n < N){
            *(float4*)(C+(long)m*ldc+n)   = make_float4(acc[i][0]*alpha,acc[i][1]*alpha,acc[i][2]*alpha,acc[i][3]*alpha);
            *(float4*)(C+(long)m*ldc+n+4) = make_float4(acc[i][4]*alpha,acc[i][5]*alpha,acc[i][6]*alpha,acc[i][7]*alpha);
        }
    }
}

// ======= fp32 SIMT NT GEMM 64x64 (R1 kernel — same k-ascending chain) ======
__global__ __launch_bounds__(256) void gemm64_nt_k(
    const float* __restrict__ A, int lda,
    const float* __restrict__ B, int ldb,
    float* __restrict__ C, int ldc,
    int M, int N, int K, float alpha)
{
    int n0 = blockIdx.x * 64, m0 = blockIdx.y * 64;
    __shared__ float As[16][64];
    __shared__ float Bs[16][64];
    int tx = threadIdx.x, ty = threadIdx.y;
    int tid = ty * 16 + tx;
    int lr = tid >> 2, lc = (tid & 3) * 4;
    float acc[4][4] = {};
    for (int k0 = 0; k0 < K; k0 += 16) {
        if (m0 + lr < M) {
            float4 v = *(const float4*)(A + (long)(m0 + lr) * lda + k0 + lc);
            As[lc][lr] = v.x; As[lc+1][lr] = v.y; As[lc+2][lr] = v.z; As[lc+3][lr] = v.w;
        } else {
            As[lc][lr] = 0.f; As[lc+1][lr] = 0.f; As[lc+2][lr] = 0.f; As[lc+3][lr] = 0.f;
        }
        if (n0 + lr < N) {
            float4 v = *(const float4*)(B + (long)(n0 + lr) * ldb + k0 + lc);
            Bs[lc][lr] = v.x; Bs[lc+1][lr] = v.y; Bs[lc+2][lr] = v.z; Bs[lc+3][lr] = v.w;
        } else {
            Bs[lc][lr] = 0.f; Bs[lc+1][lr] = 0.f; Bs[lc+2][lr] = 0.f; Bs[lc+3][lr] = 0.f;
        }
        __syncthreads();
        #pragma unroll
        for (int k = 0; k < 16; k++) {
            float4 a4 = *(const float4*)(&As[k][ty * 4]);
            float4 b4 = *(const float4*)(&Bs[k][tx * 4]);
            float a[4] = {a4.x, a4.y, a4.z, a4.w};
            float b[4] = {b4.x, b4.y, b4.z, b4.w};
            #pragma unroll
            for (int i = 0; i < 4; i++)
                #pragma unroll
                for (int j = 0; j < 4; j++)
                    acc[i][j] += a[i] * b[j];
        }
        __syncthreads();
    }
    #pragma unroll
    for (int i = 0; i < 4; i++) {
        int m = m0 + ty * 4 + i;
        if (m >= M) continue;
        #pragma unroll
        for (int j = 0; j < 4; j++) {
            int n = n0 + tx * 4 + j;
            if (n < N) C[(long)m * ldc + n] = alpha * acc[i][j];
        }
    }
}

// ---------------- cvt / norms / ropes ----------------
__global__ void cvt_hilo_k(const float* __restrict__ in, bf16* __restrict__ hi, bf16* __restrict__ lo, int n){
    int i = blockIdx.x*256 + threadIdx.x;
    if (i < n){
        float x = in[i]; bf16 h = __float2bfloat16(x);
        hi[i] = h; lo[i] = __float2bfloat16(x - __bfloat162float(h));
    }
}
__global__ void rmsnorm_k(const float* __restrict__ in, int ldi,
                          float* __restrict__ out, int ldo,
                          const float* __restrict__ w, int D){
    int s = blockIdx.x, tid = threadIdx.x;
    __shared__ float red[256];
    const float* ip = in + (long)s*ldi;
    float ss = 0.f;
    for (int d=tid; d<D; d+=256){ float v = ip[d]; ss += v*v; }
    red[tid]=ss; __syncthreads();
    for (int o=128;o>0;o>>=1){ if(tid<o) red[tid]+=red[tid+o]; __syncthreads(); }
    float scale = rsqrtf(red[0]/(float)D + 1e-6f);
    float* op = out + (long)s*ldo;
    for (int d=tid; d<D; d+=256) op[d] = ip[d]*scale*w[d];
}
__global__ void rope_q_k(float* __restrict__ q, const float* __restrict__ cs, const float* __restrict__ sn){
    int s = blockIdx.x, tid = threadIdx.x, h = tid>>5, i = tid&31;
    float c = cs[s*32+i], si = sn[s*32+i];
    float* p = q + (long)s*3072 + h*192 + 128 + 2*i;
    float x0=p[0], x1=p[1]; p[0]=x0*c-x1*si; p[1]=x0*si+x1*c;
}
__global__ void build_k_k(const float* __restrict__ kvp, const float* __restrict__ kvall,
                          float* __restrict__ kk, const float* __restrict__ cs, const float* __restrict__ sn){
    int s = blockIdx.x, h = blockIdx.y, tid = threadIdx.x;
    float* dst = kk + ((long)s*16+h)*192;
    dst[tid] = kvp[(long)s*4096 + h*256 + tid];
    if (tid < 32){
        float c = cs[s*32+tid], si = sn[s*32+tid];
        float x0 = kvall[(long)s*576+512+2*tid], x1 = kvall[(long)s*576+513+2*tid];
        dst[128+2*tid]=x0*c-x1*si; dst[129+2*tid]=x0*si+x1*c;
    }
}
__global__ void rope_qi_k(float* __restrict__ qi, const float* __restrict__ cs, const float* __restrict__ sn){
    int s = blockIdx.x, tid = threadIdx.x, h = tid>>5, d = tid&31;
    float c = cs[s*32+d], si = sn[s*32+d];
    float* p = qi + (long)s*4096 + h*128;
    float x0=p[d], x1=p[d+32]; p[d]=x0*c-x1*si; p[d+32]=x0*si+x1*c;
}
__global__ void ln_rope_ki_k(float* __restrict__ ki, const float* __restrict__ w, const float* __restrict__ b,
                             const float* __restrict__ cs, const float* __restrict__ sn){
    int s = blockIdx.x, tid = threadIdx.x;
    __shared__ float red[128]; __shared__ float buf[128];
    float v = ki[(long)s*128+tid];
    red[tid]=v; __syncthreads();
    for (int o=64;o>0;o>>=1){ if(tid<o) red[tid]+=red[tid+o]; __syncthreads(); }
    float mean = red[0]/128.f; __syncthreads();
    float d = v-mean; red[tid]=d*d; __syncthreads();
    for (int o=64;o>0;o>>=1){ if(tid<o) red[tid]+=red[tid+o]; __syncthreads(); }
    float nv = d*rsqrtf(red[0]/128.f + 1e-5f)*w[tid] + b[tid];
    buf[tid]=nv; __syncthreads();
    float out;
    if (tid<32){ float c=cs[s*32+tid], si=sn[s*32+tid]; out = buf[tid]*c - buf[tid+32]*si; }
    else if (tid<64){ int i=tid-32; float c=cs[s*32+i], si=sn[s*32+i]; out = buf[i]*si + buf[i+32]*c; }
    else out = nv;
    ki[(long)s*128+tid] = out;
}
// ---------------- indexer (fp32, double-buffered As, dynamic smem) ---------
// Per-thread arithmetic sequence identical to baseline indexer.
#define IDX_SMEM ((128*64 + 2*16*128 + 128*16) * 4)   // 57344 B
__global__ __launch_bounds__(256) void indexer_k(
    const float* __restrict__ qi, const float* __restrict__ ki,
    const float* __restrict__ wts, float* __restrict__ out){
    int t0 = blockIdx.x*64, s0 = blockIdx.y*128;
    if (t0 > s0+127) return;
    extern __shared__ float dsm[];
    float* Bs = dsm;                        // [128][64]
    float* As = dsm + 128*64;               // [2][16][128]
    float* Ws = dsm + 128*64 + 2*16*128;    // [128][16]
    int tx = threadIdx.x, ty = threadIdx.y, tid = ty*16+tx;
    {
        int t = tid>>2, kb = (tid&3)*32;
        const float* kp = ki + (long)(t0+t)*128 + kb;
        #pragma unroll
        for (int c=0; c<32; c+=4){
            float4 v = *(const float4*)(kp+c);
            Bs[(kb+c)*64+t]=v.x; Bs[(kb+c+1)*64+t]=v.y; Bs[(kb+c+2)*64+t]=v.z; Bs[(kb+c+3)*64+t]=v.w;
        }
    }
    const float scl = 0.08838834764831845f;
    float fin[8][4] = {};
    int arow = tid>>1, acol = (tid&1)*8;
    const float* qbase = qi + (long)(s0+arow)*4096 + acol;

    for (int hg=0; hg<2; hg++){
        __syncthreads();
        for (int i=tid; i<2048; i+=256)
            Ws[(i>>4)*16 + (i&15)] = wts[(long)(s0+(i>>4))*32 + hg*16 + (i&15)];
        __syncthreads();

        for (int hh=0; hh<16; hh++){
            int h = hg*16+hh;
            float acc[8][4] = {};
            // prologue: chunk 0 into buffer 0
            {
                const float* qp = qbase + h*128;
                float4 v0 = *(const float4*)(qp), v1 = *(const float4*)(qp+4);
                float* A0 = As;   // buf 0
                A0[(acol+0)*128+arow]=v0.x; A0[(acol+1)*128+arow]=v0.y; A0[(acol+2)*128+arow]=v0.z; A0[(acol+3)*128+arow]=v0.w;
                A0[(acol+4)*128+arow]=v1.x; A0[(acol+5)*128+arow]=v1.y; A0[(acol+6)*128+arow]=v1.z; A0[(acol+7)*128+arow]=v1.w;
            }
            __syncthreads();
            #pragma unroll
            for (int kc=0; kc<8; kc++){
                float4 v0, v1;
                if (kc < 7){
                    const float* qp = qbase + h*128 + (kc+1)*16;
                    v0 = *(const float4*)(qp); v1 = *(const float4*)(qp+4);
                }
                const float* Ac = As + (kc&1)*2048;
                #pragma unroll
                for (int k=0; k<16; k++){
                    float4 a0 = *(const float4*)(&Ac[k*128 + ty*8]);
                    float4 a1 = *(const float4*)(&Ac[k*128 + ty*8+4]);
                    float4 b4 = *(const float4*)(&Bs[(kc*16+k)*64 + tx*4]);
                    float a[8]={a0.x,a0.y,a0.z,a0.w,a1.x,a1.y,a1.z,a1.w};
                    float b[4]={b4.x,b4.y,b4.z,b4.w};
                    #pragma unroll
                    for (int i=0;i<8;i++)
                        #pragma unroll
                        for (int j=0;j<4;j++) acc[i][j]+=a[i]*b[j];
                }
                if (kc < 7){
                    float* An = As + ((kc+1)&1)*2048;
                    An[(acol+0)*128+arow]=v0.x; An[(acol+1)*128+arow]=v0.y; An[(acol+2)*128+arow]=v0.z; An[(acol+3)*128+arow]=v0.w;
                    An[(acol+4)*128+arow]=v1.x; An[(acol+5)*128+arow]=v1.y; An[(acol+6)*128+arow]=v1.z; An[(acol+7)*128+arow]=v1.w;
                }
                __syncthreads();
            }
            #pragma unroll
            for (int i=0;i<8;i++){
                float wv = Ws[(ty*8+i)*16 + hh];
                #pragma unroll
                for (int j=0;j<4;j++) fin[i][j]+=fmaxf(acc[i][j]*scl,0.f)*wv;
            }
        }
    }
    #pragma unroll
    for (int i=0;i<8;i++){
        float4 o = make_float4(fin[i][0],fin[i][1],fin[i][2],fin[i][3]);
        *(float4*)(out + (long)(s0+ty*8+i)*SQ + t0 + tx*4) = o;
    }
}
// ---------------- top-512 -> combined mask ----------------
__global__ __launch_bounds__(1024) void topk_mask_k(const float* __restrict__ iscore, float* __restrict__ comb){
    int s = blockIdx.x, tid = threadIdx.x;
    __shared__ float sv[2048]; __shared__ float xo[2048];
    __shared__ unsigned char sel[2048]; __shared__ int s_cnt;
    for (int t=tid; t<2048; t+=1024){
        float v = (t<=s) ? iscore[(long)s*SQ+t] : NEG_INF;
        xo[t]=v; sv[t]=v; sel[t]=0;
    }
    if (tid==0) s_cnt=0;
    __syncthreads();
    if (s <= TOPK-1){
        for (int t=tid; t<2048; t+=1024) comb[(long)s*SQ+t] = (t<=s)?0.f:NEG_INF;
        return;
    }
    for (int k=2;k<=2048;k<<=1)
        for (int j=k>>1;j>0;j>>=1){
            for (int t=tid;t<2048;t+=1024){
                int ixj = t^j;
                if (ixj>t){
                    float a=sv[t], b=sv[ixj];
                    bool asc = ((t&k)==0);
                    if (asc ? (a>b):(a<b)){ sv[t]=b; sv[ixj]=a; }
                }
            }
            __syncthreads();
        }
    float T = sv[2048-TOPK];
    int local=0;
    for (int t=tid;t<=s;t+=1024) if (xo[t]>T){ sel[t]=1; local++; }
    atomicAdd(&s_cnt, local);
    __syncthreads();
    if (tid==0){
        int quota = TOPK - s_cnt;
        for (int t=0; t<=s && quota>0; t++) if (!sel[t] && xo[t]==T){ sel[t]=1; quota--; }
    }
    __syncthreads();
    for (int t=tid;t<2048;t+=1024) comb[(long)s*SQ+t] = sel[t]?0.f:NEG_INF;
}
// ---------------- masked softmax -> bf16 hi/lo probs, range-limited --------
__global__ void softmax2_k(const float* __restrict__ scores, const float* __restrict__ comb,
                           bf16* __restrict__ phi, bf16* __restrict__ plo){
    int s = blockIdx.x, h = blockIdx.y, tid = threadIdx.x;
    long ro = ((long)h*SQ+s)*SQ;
    const float* row = scores + ro;
    const float* cm = comb + (long)s*SQ;
    int lim = ((s>>7)+1)<<7;
    __shared__ float red[256];
    float m = NEG_INF;
    for (int t=tid;t<lim;t+=256) if (cm[t]==0.f) m = fmaxf(m, row[t]);
    red[tid]=m; __syncthreads();
    for (int o=128;o>0;o>>=1){ if(tid<o) red[tid]=fmaxf(red[tid],red[tid+o]); __syncthreads(); }
    m = red[0]; __syncthreads();
    float sum=0.f;
    for (int t=tid;t<lim;t+=256)
        if (cm[t]==0.f) sum += expf(row[t]-m);
    red[tid]=sum; __syncthreads();
    for (int o=128;o>0;o>>=1){ if(tid<o) red[tid]+=red[tid+o]; __syncthreads(); }
    float inv = 1.f/red[0];
    for (int t=tid;t<lim;t+=256){
        float p = (cm[t]==0.f) ? expf(row[t]-m)*inv : 0.f;
        bf16 hb = __float2bfloat16(p);
        phi[ro+t] = hb;
        plo[ro+t] = __float2bfloat16(p - __bfloat162float(hb));
    }
}
// ---------------- v^T build: kvp -> vT[h][n][k] bf16 hi/lo -----------------
__global__ void build_vT_k(const float* __restrict__ kvp, bf16* __restrict__ vhi, bf16* __restrict__ vlo){
    int s = blockIdx.x*256 + threadIdx.x;
    int n = blockIdx.y, h = blockIdx.z;
    float v = kvp[(long)s*4096 + h*256 + 128 + n];
    long o = ((long)h*128 + n)*2048 + s;
    bf16 hb = __float2bfloat16(v);
    vhi[o] = hb; vlo[o] = __float2bfloat16(v - __bfloat162float(hb));
}

// ================= host =================
static void cvt(const float* in, bf16* hi, bf16* lo, int n){
    cvt_hilo_k<<<(n+255)/256, 256>>>(in, hi, lo, n);
}
#define GSYM(p, s) cudaGetSymbolAddress((void**)&p, s)

extern "C" void kernel_launch(void* const* d_in, const int* in_sizes, int n_in,
                              void* d_out, int out_size)
{
    if (n_in < 16) return;
    const float *hidden,*wq_a,*q_norm_w,*wq_b,*wkv_a,*kv_norm_w,*wkv_b,*wo;
    const float *idx_wq_b,*idx_wk,*idx_kn_w,*idx_kn_b,*idx_wproj,*fcos,*fsin;
    if (in_sizes[1] == 1536*2048){
        hidden=(const float*)d_in[0];  wq_a=(const float*)d_in[1];
        q_norm_w=(const float*)d_in[2]; wq_b=(const float*)d_in[3];
        wkv_a=(const float*)d_in[4];   kv_norm_w=(const float*)d_in[5];
        wkv_b=(const float*)d_in[6];   wo=(const float*)d_in[7];
        idx_wq_b=(const float*)d_in[8]; idx_wk=(const float*)d_in[9];
        idx_kn_w=(const float*)d_in[10]; idx_kn_b=(const float*)d_in[11];
        idx_wproj=(const float*)d_in[12]; fcos=(const float*)d_in[13]; fsin=(const float*)d_in[14];
    } else {
        hidden=(const float*)d_in[0]; fcos=(const float*)d_in[1]; fsin=(const float*)d_in[2];
        wq_a=(const float*)d_in[4];   q_norm_w=(const float*)d_in[5];
        wq_b=(const float*)d_in[6];   wkv_a=(const float*)d_in[7];
        kv_norm_w=(const float*)d_in[8]; wkv_b=(const float*)d_in[9];
        wo=(const float*)d_in[10];    idx_wq_b=(const float*)d_in[11];
        idx_wk=(const float*)d_in[12]; idx_kn_w=(const float*)d_in[13];
        idx_kn_b=(const float*)d_in[14]; idx_wproj=(const float*)d_in[15];
    }

    float *qr,*q,*kvall,*kv,*kvp,*k,*qi,*ki,*wts,*iscore,*comb,*scores,*attnout;
    GSYM(qr,g_qr); GSYM(q,g_q); GSYM(kvall,g_kvall); GSYM(kv,g_kv); GSYM(kvp,g_kvp); GSYM(k,g_k);
    GSYM(qi,g_qi); GSYM(ki,g_ki); GSYM(wts,g_wts); GSYM(iscore,g_iscore);
    GSYM(comb,g_comb); GSYM(scores,g_scores); GSYM(attnout,g_attnout);
    bf16 *h_hi,*h_lo,*wqb_hi,*wqb_lo,*wkva_hi,*wkva_lo,*wkvb_hi,*wkvb_lo,*wo_hi,*wo_lo;
    bf16 *qrn_hi,*qrn_lo,*kvn_hi,*kvn_lo,*qh_hi,*qh_lo,*kh_hi,*kh_lo,*at_hi,*at_lo;
    bf16 *p_hi,*p_lo,*vT_hi,*vT_lo;
    GSYM(h_hi,g_h_hi); GSYM(h_lo,g_h_lo);
    GSYM(wqb_hi,g_wqb_hi); GSYM(wqb_lo,g_wqb_lo); GSYM(wkva_hi,g_wkva_hi); GSYM(wkva_lo,g_wkva_lo);
    GSYM(wkvb_hi,g_wkvb_hi); GSYM(wkvb_lo,g_wkvb_lo); GSYM(wo_hi,g_wo_hi); GSYM(wo_lo,g_wo_lo);
    GSYM(qrn_hi,g_qrn_hi); GSYM(qrn_lo,g_qrn_lo); GSYM(kvn_hi,g_kvn_hi); GSYM(kvn_lo,g_kvn_lo);
    GSYM(qh_hi,g_qh_hi); GSYM(qh_lo,g_qh_lo); GSYM(kh_hi,g_kh_hi); GSYM(kh_lo,g_kh_lo);
    GSYM(at_hi,g_at_hi); GSYM(at_lo,g_at_lo);
    GSYM(p_hi,g_p_hi); GSYM(p_lo,g_p_lo); GSYM(vT_hi,g_vT_hi); GSYM(vT_lo,g_vT_lo);
    float* outp = (float*)d_out;

    cudaFuncSetAttribute(gemm_mma_nt, cudaFuncAttributeMaxDynamicSharedMemorySize, MMA_SMEM);
    cudaFuncSetAttribute(indexer_k, cudaFuncAttributeMaxDynamicSharedMemorySize, IDX_SMEM);
    dim3 blk(16,16);
    const float inv_sqrt192 = 0.07216878364870323f;
    const float inv_sqrt32  = 0.17677669529663687f;

    // ---- indexer-critical chain: EXACT fp32 baseline numerics ----
    gemm_nt_k<<<dim3(12,16,1),blk>>>(hidden,0,DMM, wq_a,0,DMM, qr,0,QRR, SQ,QRR,DMM,1.f,0);
    rmsnorm_k<<<SQ,256>>>(qr,QRR, qr,QRR, q_norm_w,QRR);
    gemm_nt_k<<<dim3(32,16,1),blk>>>(qr,0,QRR, idx_wq_b,0,QRR, qi,0,4096, SQ,4096,QRR,1.f,0);
    gemm64_nt_k<<<dim3(2,32),blk>>>(hidden,DMM, idx_wk,DMM, ki,128, SQ,128,DMM,1.f);
    gemm64_nt_k<<<dim3(1,32),blk>>>(hidden,DMM, idx_wproj,DMM, wts,32, SQ,32,DMM,inv_sqrt32);
    rope_qi_k<<<SQ,1024>>>(qi,fcos,fsin);
    ln_rope_ki_k<<<SQ,128>>>(ki,idx_kn_w,idx_kn_b,fcos,fsin);
    indexer_k<<<dim3(SQ/64,SQ/128),blk,IDX_SMEM>>>(qi,ki,wts,iscore);
    topk_mask_k<<<SQ,1024>>>(iscore,comb);

    // ---- smooth path: bf16x3 mma ----
    cvt(hidden,h_hi,h_lo,2048*2048);
    cvt(wkv_a,wkva_hi,wkva_lo,576*2048);
    cvt(wq_b,wqb_hi,wqb_lo,3072*1536);
    cvt(wkv_b,wkvb_hi,wkvb_lo,4096*512);
    cvt(wo,wo_hi,wo_lo,2048*2048);
    cvt(qr,qrn_hi,qrn_lo,2048*1536);

    gemm_mma_nt<<<dim3(5,16,1),256,MMA_SMEM>>>(h_hi,h_lo,0,2048, wkva_hi,wkva_lo,0,2048, kvall,0,576, 576,2048,1.f,0);
    rmsnorm_k<<<SQ,256>>>(kvall,576, kv,KRR, kv_norm_w,KRR);
    cvt(kv,kvn_hi,kvn_lo,2048*512);
    gemm_mma_nt<<<dim3(32,16,1),256,MMA_SMEM>>>(kvn_hi,kvn_lo,0,512, wkvb_hi,wkvb_lo,0,512, kvp,0,4096, 4096,512,1.f,0);
    gemm_mma_nt<<<dim3(24,16,1),256,MMA_SMEM>>>(qrn_hi,qrn_lo,0,1536, wqb_hi,wqb_lo,0,1536, q,0,3072, 3072,1536,1.f,0);
    rope_q_k<<<SQ,512>>>(q,fcos,fsin);
    build_k_k<<<dim3(SQ,NH),128>>>(kvp,kvall,k,fcos,fsin);
    cvt(q,qh_hi,qh_lo,2048*3072);
    cvt(k,kh_hi,kh_lo,2048*3072);
    gemm_mma_nt<<<dim3(16,16,16),256,MMA_SMEM>>>(qh_hi,qh_lo,192,3072, kh_hi,kh_lo,192,3072,
                                                 scores,(long)SQ*SQ,SQ, SQ,192,inv_sqrt192,1);
    softmax2_k<<<dim3(SQ,NH),256>>>(scores,comb,p_hi,p_lo);
    build_vT_k<<<dim3(8,128,16),256>>>(kvp, vT_hi, vT_lo);
    gemm_mma_nt<<<dim3(1,16,16),256,MMA_SMEM>>>(p_hi,p_lo,(long)SQ*SQ,SQ, vT_hi,vT_lo,(long)128*2048,2048,
                                                attnout,128,2048, 128,2048,1.f,2);
    cvt(attnout,at_hi,at_lo,2048*2048);
    gemm_mma_nt<<<dim3(16,16,1),256,MMA_SMEM>>>(at_hi,at_lo,0,2048, wo_hi,wo_lo,0,2048, outp,0,2048, 2048,2048,1.f,0);
}

// round 9
// speedup vs baseline: 1.0869x; 1.0869x over previous
#include <cuda_runtime.h>
#include <cuda_bf16.h>
#include <math.h>
#include <stdint.h>

#define SQ 2048
#define NH 16
#define QRR 1536
#define KRR 512
#define TOPK 512
#define DMM 2048
#define NEG_INF (__int_as_float(0xff800000))
typedef __nv_bfloat16 bf16;

// ---------------- fp32 scratch ----------------
__device__ float g_qr[SQ*QRR];
__device__ float g_q[SQ*NH*192];
__device__ float g_kvall[SQ*576];
__device__ float g_kv[SQ*KRR];
__device__ float g_kvp[SQ*NH*256];
__device__ float g_k[SQ*NH*192];
__device__ float g_qi[SQ*32*128];
__device__ float g_ki[SQ*128];
__device__ float g_wts[SQ*32];
__device__ float g_iscore[SQ*SQ];
__device__ float g_comb[SQ*SQ];
__device__ float g_scores[67108864];
__device__ float g_attnout[SQ*DMM];
// ---------------- bf16 hi/lo scratch (smooth path only) ----------------
__device__ bf16 g_h_hi[2048*2048],  g_h_lo[2048*2048];
__device__ bf16 g_wqb_hi[3072*1536],g_wqb_lo[3072*1536];
__device__ bf16 g_wkva_hi[576*2048],g_wkva_lo[576*2048];
__device__ bf16 g_wkvb_hi[4096*512],g_wkvb_lo[4096*512];
__device__ bf16 g_wo_hi[2048*2048], g_wo_lo[2048*2048];
__device__ bf16 g_qrn_hi[2048*1536],g_qrn_lo[2048*1536];
__device__ bf16 g_kvn_hi[2048*512], g_kvn_lo[2048*512];
__device__ bf16 g_qh_hi[2048*3072], g_qh_lo[2048*3072];
__device__ bf16 g_kh_hi[2048*3072], g_kh_lo[2048*3072];
__device__ bf16 g_at_hi[2048*2048], g_at_lo[2048*2048];
__device__ bf16 g_p_hi[67108864],   g_p_lo[67108864];
__device__ bf16 g_vT_hi[16*128*2048], g_vT_lo[16*128*2048];

// ================= mma.sync helpers =================
__device__ __forceinline__ uint32_t smem_u32(const void* p){
    uint32_t a; asm("{ .reg .u64 t; cvta.to.shared.u64 t, %1; cvt.u32.u64 %0, t; }":"=r"(a):"l"(p)); return a;
}
#define LDSM4(R, ADDR) asm volatile( \
    "ldmatrix.sync.aligned.m8n8.x4.shared.b16 {%0,%1,%2,%3}, [%4];" \
    : "=r"((R)[0]),"=r"((R)[1]),"=r"((R)[2]),"=r"((R)[3]) : "r"(ADDR))
#define MMA16816(D, A, B) asm volatile( \
    "mma.sync.aligned.m16n8k16.row.col.f32.bf16.bf16.f32 " \
    "{%0,%1,%2,%3}, {%4,%5,%6,%7}, {%8,%9}, {%0,%1,%2,%3};" \
    : "+f"((D)[0]),"+f"((D)[1]),"+f"((D)[2]),"+f"((D)[3]) \
    : "r"((A)[0]),"r"((A)[1]),"r"((A)[2]),"r"((A)[3]), "r"((B)[0]),"r"((B)[1]))

// ======= bf16x3 NT GEMM via mma.sync (smooth path) =======
// causal: 0=dense, 1=skip above-diagonal tiles, 2=K capped at m0+128 (PV)
#define LSTR 72
#define MMA_SMEM (4*128*LSTR*2)
__global__ __launch_bounds__(256) void gemm_mma_nt(
    const bf16* __restrict__ Ah, const bf16* __restrict__ Al, long sa, int lda,
    const bf16* __restrict__ Bh, const bf16* __restrict__ Bl, long sb, int ldb,
    float* __restrict__ C, long sc, int ldc, int N, int K, float alpha, int causal)
{
    int n0 = blockIdx.x*128, m0 = blockIdx.y*128;
    if (causal == 1 && n0 > m0+127) return;
    int Keff = K;
    if (causal == 2 && m0+128 < Keff) Keff = m0+128;
    Ah += (long)blockIdx.z*sa; Al += (long)blockIdx.z*sa;
    Bh += (long)blockIdx.z*sb; Bl += (long)blockIdx.z*sb;
    C  += (long)blockIdx.z*sc;

    extern __shared__ bf16 sm[];
    bf16 *sAh = sm, *sAl = sm + 128*LSTR, *sBh = sm + 2*128*LSTR, *sBl = sm + 3*128*LSTR;
    int tid = threadIdx.x, lane = tid & 31, wid = tid >> 5;
    int wm = (wid >> 1) * 32, wn = (wid & 1) * 64;
    float acc[2][8][4] = {};

    for (int kc = 0; kc < Keff; kc += 64){
        __syncthreads();
        #pragma unroll
        for (int it = 0; it < 4; it++){
            int c = tid + it*256, row = c >> 3, cb = (c & 7) * 8;
            long ga = (long)(m0+row)*lda + kc + cb;
            *(int4*)&sAh[row*LSTR + cb] = *(const int4*)(Ah + ga);
            *(int4*)&sAl[row*LSTR + cb] = *(const int4*)(Al + ga);
            int4 vh = make_int4(0,0,0,0), vl = vh;
            if (n0 + row < N){
                long gb = (long)(n0+row)*ldb + kc + cb;
                vh = *(const int4*)(Bh + gb); vl = *(const int4*)(Bl + gb);
            }
            *(int4*)&sBh[row*LSTR + cb] = vh;
            *(int4*)&sBl[row*LSTR + cb] = vl;
        }
        __syncthreads();

        int r = lane & 15, ko = (lane >> 4) * 8;
        #pragma unroll
        for (int ks = 0; ks < 4; ks++){
            uint32_t ah[2][4], al[2][4], bh[8][2], bl[8][2];
            #pragma unroll
            for (int mi = 0; mi < 2; mi++){
                uint32_t ad = smem_u32(&sAh[(wm + mi*16 + r)*LSTR + ks*16 + ko]);
                LDSM4(ah[mi], ad);
                ad = smem_u32(&sAl[(wm + mi*16 + r)*LSTR + ks*16 + ko]);
                LDSM4(al[mi], ad);
            }
            #pragma unroll
            for (int np = 0; np < 4; np++){
                uint32_t t4[4];
                uint32_t bd = smem_u32(&sBh[(wn + np*16 + r)*LSTR + ks*16 + ko]);
                LDSM4(t4, bd);
                bh[2*np][0]=t4[0]; bh[2*np][1]=t4[2]; bh[2*np+1][0]=t4[1]; bh[2*np+1][1]=t4[3];
                bd = smem_u32(&sBl[(wn + np*16 + r)*LSTR + ks*16 + ko]);
                LDSM4(t4, bd);
                bl[2*np][0]=t4[0]; bl[2*np][1]=t4[2]; bl[2*np+1][0]=t4[1]; bl[2*np+1][1]=t4[3];
            }
            #pragma unroll
            for (int mi = 0; mi < 2; mi++)
                #pragma unroll
                for (int ni = 0; ni < 8; ni++){
                    MMA16816(acc[mi][ni], ah[mi], bh[ni]);
                    MMA16816(acc[mi][ni], ah[mi], bl[ni]);
                    MMA16816(acc[mi][ni], al[mi], bh[ni]);
                }
        }
    }
    #pragma unroll
    for (int mi = 0; mi < 2; mi++){
        int mrow = m0 + wm + mi*16 + (lane >> 2);
        #pragma unroll
        for (int ni = 0; ni < 8; ni++){
            int n = n0 + wn + ni*8 + (lane & 3)*2;
            if (n < N){
                *(float2*)(C + (long)mrow*ldc + n)     = make_float2(alpha*acc[mi][ni][0], alpha*acc[mi][ni][1]);
                *(float2*)(C + (long)(mrow+8)*ldc + n) = make_float2(alpha*acc[mi][ni][2], alpha*acc[mi][ni][3]);
            }
        }
    }
}

// ======= fp32 SIMT NT GEMM 128x128 (bit-identical baseline) =======
// fused=0: plain. fused=1: blockIdx.x selects {wq_a->qr | idx_wk->ki | idx_wproj->wts}
__device__ __forceinline__ void gemm_core(
    const float* A, int lda, const float* B, int ldb,
    float* C, int ldc, int M, int N, int K, float alpha, int m0, int n0)
{
    __shared__ float As[2][16][128];
    __shared__ float Bs[2][16][128];
    int tx = threadIdx.x, ty = threadIdx.y, tid = ty*16+tx;
    int lrow = tid>>1, lcol = (tid&1)*8;
    const float* Ap = A + (long)(m0+lrow)*lda + lcol;
    const float* Bp = B + (long)(n0+lrow)*ldb + lcol;
    bool aval = (m0+lrow) < M, bval = (n0+lrow) < N;
    float4 ra0, ra1, rb0, rb1;
    const float4 z4 = make_float4(0.f,0.f,0.f,0.f);
    ra0 = aval ? *(const float4*)(Ap)   : z4;
    ra1 = aval ? *(const float4*)(Ap+4) : z4;
    rb0 = bval ? *(const float4*)(Bp)   : z4;
    rb1 = bval ? *(const float4*)(Bp+4) : z4;
    As[0][lcol+0][lrow]=ra0.x; As[0][lcol+1][lrow]=ra0.y; As[0][lcol+2][lrow]=ra0.z; As[0][lcol+3][lrow]=ra0.w;
    As[0][lcol+4][lrow]=ra1.x; As[0][lcol+5][lrow]=ra1.y; As[0][lcol+6][lrow]=ra1.z; As[0][lcol+7][lrow]=ra1.w;
    Bs[0][lcol+0][lrow]=rb0.x; Bs[0][lcol+1][lrow]=rb0.y; Bs[0][lcol+2][lrow]=rb0.z; Bs[0][lcol+3][lrow]=rb0.w;
    Bs[0][lcol+4][lrow]=rb1.x; Bs[0][lcol+5][lrow]=rb1.y; Bs[0][lcol+6][lrow]=rb1.z; Bs[0][lcol+7][lrow]=rb1.w;
    __syncthreads();
    float acc[8][8] = {};
    int nk = K>>4;
    for (int kt=0; kt<nk; kt++){
        int cur = kt&1;
        if (kt+1<nk){
            const float* Ap2 = Ap + (kt+1)*16;
            const float* Bp2 = Bp + (kt+1)*16;
            ra0 = aval ? *(const float4*)(Ap2)   : z4;
            ra1 = aval ? *(const float4*)(Ap2+4) : z4;
            rb0 = bval ? *(const float4*)(Bp2)   : z4;
            rb1 = bval ? *(const float4*)(Bp2+4) : z4;
        }
        #pragma unroll
        for (int k=0;k<16;k++){
            float4 a0=*(const float4*)(&As[cur][k][ty*8]);
            float4 a1=*(const float4*)(&As[cur][k][ty*8+4]);
            float4 b0=*(const float4*)(&Bs[cur][k][tx*8]);
            float4 b1=*(const float4*)(&Bs[cur][k][tx*8+4]);
            float a[8]={a0.x,a0.y,a0.z,a0.w,a1.x,a1.y,a1.z,a1.w};
            float b[8]={b0.x,b0.y,b0.z,b0.w,b1.x,b1.y,b1.z,b1.w};
            #pragma unroll
            for (int i=0;i<8;i++)
                #pragma unroll
                for (int j=0;j<8;j++) acc[i][j]+=a[i]*b[j];
        }
        if (kt+1<nk){
            int nx = cur^1;
            As[nx][lcol+0][lrow]=ra0.x; As[nx][lcol+1][lrow]=ra0.y; As[nx][lcol+2][lrow]=ra0.z; As[nx][lcol+3][lrow]=ra0.w;
            As[nx][lcol+4][lrow]=ra1.x; As[nx][lcol+5][lrow]=ra1.y; As[nx][lcol+6][lrow]=ra1.z; As[nx][lcol+7][lrow]=ra1.w;
            Bs[nx][lcol+0][lrow]=rb0.x; Bs[nx][lcol+1][lrow]=rb0.y; Bs[nx][lcol+2][lrow]=rb0.z; Bs[nx][lcol+3][lrow]=rb0.w;
            Bs[nx][lcol+4][lrow]=rb1.x; Bs[nx][lcol+5][lrow]=rb1.y; Bs[nx][lcol+6][lrow]=rb1.z; Bs[nx][lcol+7][lrow]=rb1.w;
        }
        __syncthreads();
    }
    #pragma unroll
    for (int i=0;i<8;i++){
        int m = m0+ty*8+i;
        if (m >= M) continue;
        int n = n0+tx*8;
        if (n < N){
            *(float4*)(C+(long)m*ldc+n)   = make_float4(acc[i][0]*alpha,acc[i][1]*alpha,acc[i][2]*alpha,acc[i][3]*alpha);
            *(float4*)(C+(long)m*ldc+n+4) = make_float4(acc[i][4]*alpha,acc[i][5]*alpha,acc[i][6]*alpha,acc[i][7]*alpha);
        }
    }
}

__global__ __launch_bounds__(256) void gemm_nt_k(
    const float* __restrict__ A, long sa, int lda,
    const float* __restrict__ B, long sb, int ldb,
    float* __restrict__ C, long sc, int ldc,
    int M, int N, int K, float alpha, int causal)
{
    int n0 = blockIdx.x*128, m0 = blockIdx.y*128;
    if (causal && n0 > m0+127) return;
    gemm_core(A + (long)blockIdx.z*sa, lda, B + (long)blockIdx.z*sb, ldb,
              C + (long)blockIdx.z*sc, ldc, M, N, K, alpha, m0, n0);
}

// fused qr+ki+wts (shared A=hidden, K=2048): tiles 0-11 -> qr, 12 -> ki, 13 -> wts
__global__ __launch_bounds__(256) void gemm_qr_fused_k(
    const float* __restrict__ hidden,
    const float* __restrict__ wq_a, float* __restrict__ qr,
    const float* __restrict__ idx_wk, float* __restrict__ ki,
    const float* __restrict__ idx_wproj, float* __restrict__ wts, float alpha2)
{
    int bx = blockIdx.x, m0 = blockIdx.y*128;
    if (bx < 12)      gemm_core(hidden, DMM, wq_a, DMM, qr, QRR, SQ, QRR, DMM, 1.f, m0, bx*128);
    else if (bx == 12) gemm_core(hidden, DMM, idx_wk, DMM, ki, 128, SQ, 128, DMM, 1.f, m0, 0);
    else               gemm_core(hidden, DMM, idx_wproj, DMM, wts, 32, SQ, 32, DMM, alpha2, m0, 0);
}

// ---------------- cvt / norms / ropes ----------------
__global__ void cvt_hilo_k(const float* __restrict__ in, bf16* __restrict__ hi, bf16* __restrict__ lo, int n){
    int i = blockIdx.x*256 + threadIdx.x;
    if (i < n){
        float x = in[i]; bf16 h = __float2bfloat16(x);
        hi[i] = h; lo[i] = __float2bfloat16(x - __bfloat162float(h));
    }
}
__global__ void rmsnorm_k(const float* __restrict__ in, int ldi,
                          float* __restrict__ out, int ldo,
                          const float* __restrict__ w, int D){
    int s = blockIdx.x, tid = threadIdx.x;
    __shared__ float red[256];
    const float* ip = in + (long)s*ldi;
    float ss = 0.f;
    for (int d=tid; d<D; d+=256){ float v = ip[d]; ss += v*v; }
    red[tid]=ss; __syncthreads();
    for (int o=128;o>0;o>>=1){ if(tid<o) red[tid]+=red[tid+o]; __syncthreads(); }
    float scale = rsqrtf(red[0]/(float)D + 1e-6f);
    float* op = out + (long)s*ldo;
    for (int d=tid; d<D; d+=256) op[d] = ip[d]*scale*w[d];
}
__global__ void rope_q_k(float* __restrict__ q, const float* __restrict__ cs, const float* __restrict__ sn){
    int s = blockIdx.x, tid = threadIdx.x, h = tid>>5, i = tid&31;
    float c = cs[s*32+i], si = sn[s*32+i];
    float* p = q + (long)s*3072 + h*192 + 128 + 2*i;
    float x0=p[0], x1=p[1]; p[0]=x0*c-x1*si; p[1]=x0*si+x1*c;
}
__global__ void build_k_k(const float* __restrict__ kvp, const float* __restrict__ kvall,
                          float* __restrict__ kk, const float* __restrict__ cs, const float* __restrict__ sn){
    int s = blockIdx.x, h = blockIdx.y, tid = threadIdx.x;
    float* dst = kk + ((long)s*16+h)*192;
    dst[tid] = kvp[(long)s*4096 + h*256 + tid];
    if (tid < 32){
        float c = cs[s*32+tid], si = sn[s*32+tid];
        float x0 = kvall[(long)s*576+512+2*tid], x1 = kvall[(long)s*576+513+2*tid];
        dst[128+2*tid]=x0*c-x1*si; dst[129+2*tid]=x0*si+x1*c;
    }
}
__global__ void rope_qi_k(float* __restrict__ qi, const float* __restrict__ cs, const float* __restrict__ sn){
    int s = blockIdx.x, tid = threadIdx.x, h = tid>>5, d = tid&31;
    float c = cs[s*32+d], si = sn[s*32+d];
    float* p = qi + (long)s*4096 + h*128;
    float x0=p[d], x1=p[d+32]; p[d]=x0*c-x1*si; p[d+32]=x0*si+x1*c;
}
__global__ void ln_rope_ki_k(float* __restrict__ ki, const float* __restrict__ w, const float* __restrict__ b,
                             const float* __restrict__ cs, const float* __restrict__ sn){
    int s = blockIdx.x, tid = threadIdx.x;
    __shared__ float red[128]; __shared__ float buf[128];
    float v = ki[(long)s*128+tid];
    red[tid]=v; __syncthreads();
    for (int o=64;o>0;o>>=1){ if(tid<o) red[tid]+=red[tid+o]; __syncthreads(); }
    float mean = red[0]/128.f; __syncthreads();
    float d = v-mean; red[tid]=d*d; __syncthreads();
    for (int o=64;o>0;o>>=1){ if(tid<o) red[tid]+=red[tid+o]; __syncthreads(); }
    float nv = d*rsqrtf(red[0]/128.f + 1e-5f)*w[tid] + b[tid];
    buf[tid]=nv; __syncthreads();
    float out;
    if (tid<32){ float c=cs[s*32+tid], si=sn[s*32+tid]; out = buf[tid]*c - buf[tid+32]*si; }
    else if (tid<64){ int i=tid-32; float c=cs[s*32+i], si=sn[s*32+i]; out = buf[i]*si + buf[i+32]*c; }
    else out = nv;
    ki[(long)s*128+tid] = out;
}
// ---------------- indexer (fp32 SIMT, R7 known-good static version) --------
__global__ __launch_bounds__(256) void indexer_k(
    const float* __restrict__ qi, const float* __restrict__ ki,
    const float* __restrict__ wts, float* __restrict__ out){
    int t0 = blockIdx.x*64, s0 = blockIdx.y*128;
    if (t0 > s0+127) return;
    __shared__ float Bs[128][64]; __shared__ float As[16][128]; __shared__ float Ws[128][16];
    int tx = threadIdx.x, ty = threadIdx.y, tid = ty*16+tx;
    {
        int t = tid>>2, kb = (tid&3)*32;
        const float* kp = ki + (long)(t0+t)*128 + kb;
        #pragma unroll
        for (int c=0; c<32; c+=4){
            float4 v = *(const float4*)(kp+c);
            Bs[kb+c][t]=v.x; Bs[kb+c+1][t]=v.y; Bs[kb+c+2][t]=v.z; Bs[kb+c+3][t]=v.w;
        }
    }
    const float scl = 0.08838834764831845f;
    float fin[8][4] = {};
    int arow = tid>>1, acol = (tid&1)*8;
    for (int hg=0; hg<2; hg++){
        __syncthreads();
        for (int i=tid; i<2048; i+=256)
            Ws[i>>4][i&15] = wts[(long)(s0+(i>>4))*32 + hg*16 + (i&15)];
        __syncthreads();
        for (int hh=0; hh<16; hh++){
            int h = hg*16+hh;
            float acc[8][4] = {};
            #pragma unroll
            for (int kc=0; kc<8; kc++){
                const float* qp = qi + (long)(s0+arow)*4096 + h*128 + kc*16 + acol;
                float4 v0 = *(const float4*)(qp), v1 = *(const float4*)(qp+4);
                __syncthreads();
                As[acol+0][arow]=v0.x; As[acol+1][arow]=v0.y; As[acol+2][arow]=v0.z; As[acol+3][arow]=v0.w;
                As[acol+4][arow]=v1.x; As[acol+5][arow]=v1.y; As[acol+6][arow]=v1.z; As[acol+7][arow]=v1.w;
                __syncthreads();
                #pragma unroll
                for (int k=0; k<16; k++){
                    float4 a0 = *(const float4*)(&As[k][ty*8]);
                    float4 a1 = *(const float4*)(&As[k][ty*8+4]);
                    float4 b4 = *(const float4*)(&Bs[kc*16+k][tx*4]);
                    float a[8]={a0.x,a0.y,a0.z,a0.w,a1.x,a1.y,a1.z,a1.w};
                    float b[4]={b4.x,b4.y,b4.z,b4.w};
                    #pragma unroll
                    for (int i=0;i<8;i++)
                        #pragma unroll
                        for (int j=0;j<4;j++) acc[i][j]+=a[i]*b[j];
                }
            }
            #pragma unroll
            for (int i=0;i<8;i++){
                float wv = Ws[ty*8+i][hh];
                #pragma unroll
                for (int j=0;j<4;j++) fin[i][j]+=fmaxf(acc[i][j]*scl,0.f)*wv;
            }
        }
    }
    #pragma unroll
    for (int i=0;i<8;i++){
        float4 o = make_float4(fin[i][0],fin[i][1],fin[i][2],fin[i][3]);
        *(float4*)(out + (long)(s0+ty*8+i)*SQ + t0 + tx*4) = o;
    }
}
// ---------------- top-512 -> combined mask ----------------
__global__ __launch_bounds__(1024) void topk_mask_k(const float* __restrict__ iscore, float* __restrict__ comb){
    int s = blockIdx.x, tid = threadIdx.x;
    __shared__ float sv[2048]; __shared__ float xo[2048];
    __shared__ unsigned char sel[2048]; __shared__ int s_cnt;
    for (int t=tid; t<2048; t+=1024){
        float v = (t<=s) ? iscore[(long)s*SQ+t] : NEG_INF;
        xo[t]=v; sv[t]=v; sel[t]=0;
    }
    if (tid==0) s_cnt=0;
    __syncthreads();
    if (s <= TOPK-1){
        for (int t=tid; t<2048; t+=1024) comb[(long)s*SQ+t] = (t<=s)?0.f:NEG_INF;
        return;
    }
    for (int k=2;k<=2048;k<<=1)
        for (int j=k>>1;j>0;j>>=1){
            for (int t=tid;t<2048;t+=1024){
                int ixj = t^j;
                if (ixj>t){
                    float a=sv[t], b=sv[ixj];
                    bool asc = ((t&k)==0);
                    if (asc ? (a>b):(a<b)){ sv[t]=b; sv[ixj]=a; }
                }
            }
            __syncthreads();
        }
    float T = sv[2048-TOPK];
    int local=0;
    for (int t=tid;t<=s;t+=1024) if (xo[t]>T){ sel[t]=1; local++; }
    atomicAdd(&s_cnt, local);
    __syncthreads();
    if (tid==0){
        int quota = TOPK - s_cnt;
        for (int t=0; t<=s && quota>0; t++) if (!sel[t] && xo[t]==T){ sel[t]=1; quota--; }
    }
    __syncthreads();
    for (int t=tid;t<2048;t+=1024) comb[(long)s*SQ+t] = sel[t]?0.f:NEG_INF;
}
// ---------------- masked softmax -> bf16 hi/lo probs, range-limited --------
__global__ void softmax2_k(const float* __restrict__ scores, const float* __restrict__ comb,
                           bf16* __restrict__ phi, bf16* __restrict__ plo){
    int s = blockIdx.x, h = blockIdx.y, tid = threadIdx.x;
    long ro = ((long)h*SQ+s)*SQ;
    const float* row = scores + ro;
    const float* cm = comb + (long)s*SQ;
    int lim = ((s>>7)+1)<<7;
    __shared__ float red[256];
    float m = NEG_INF;
    for (int t=tid;t<lim;t+=256) if (cm[t]==0.f) m = fmaxf(m, row[t]);
    red[tid]=m; __syncthreads();
    for (int o=128;o>0;o>>=1){ if(tid<o) red[tid]=fmaxf(red[tid],red[tid+o]); __syncthreads(); }
    m = red[0]; __syncthreads();
    float sum=0.f;
    for (int t=tid;t<lim;t+=256)
        if (cm[t]==0.f) sum += expf(row[t]-m);
    red[tid]=sum; __syncthreads();
    for (int o=128;o>0;o>>=1){ if(tid<o) red[tid]+=red[tid+o]; __syncthreads(); }
    float inv = 1.f/red[0];
    for (int t=tid;t<lim;t+=256){
        float p = (cm[t]==0.f) ? expf(row[t]-m)*inv : 0.f;
        bf16 hb = __float2bfloat16(p);
        phi[ro+t] = hb;
        plo[ro+t] = __float2bfloat16(p - __bfloat162float(hb));
    }
}
// ---------------- v^T build: kvp -> vT[h][n][k] bf16 hi/lo -----------------
__global__ void build_vT_k(const float* __restrict__ kvp, bf16* __restrict__ vhi, bf16* __restrict__ vlo){
    int s = blockIdx.x*256 + threadIdx.x;
    int n = blockIdx.y, h = blockIdx.z;
    float v = kvp[(long)s*4096 + h*256 + 128 + n];
    long o = ((long)h*128 + n)*2048 + s;
    bf16 hb = __float2bfloat16(v);
    vhi[o] = hb; vlo[o] = __float2bfloat16(v - __bfloat162float(hb));
}

// ================= host =================
static void cvt(const float* in, bf16* hi, bf16* lo, int n){
    cvt_hilo_k<<<(n+255)/256, 256>>>(in, hi, lo, n);
}
#define GSYM(p, s) cudaGetSymbolAddress((void**)&p, s)

extern "C" void kernel_launch(void* const* d_in, const int* in_sizes, int n_in,
                              void* d_out, int out_size)
{
    if (n_in < 16) return;
    const float *hidden,*wq_a,*q_norm_w,*wq_b,*wkv_a,*kv_norm_w,*wkv_b,*wo;
    const float *idx_wq_b,*idx_wk,*idx_kn_w,*idx_kn_b,*idx_wproj,*fcos,*fsin;
    if (in_sizes[1] == 1536*2048){
        hidden=(const float*)d_in[0];  wq_a=(const float*)d_in[1];
        q_norm_w=(const float*)d_in[2]; wq_b=(const float*)d_in[3];
        wkv_a=(const float*)d_in[4];   kv_norm_w=(const float*)d_in[5];
        wkv_b=(const float*)d_in[6];   wo=(const float*)d_in[7];
        idx_wq_b=(const float*)d_in[8]; idx_wk=(const float*)d_in[9];
        idx_kn_w=(const float*)d_in[10]; idx_kn_b=(const float*)d_in[11];
        idx_wproj=(const float*)d_in[12]; fcos=(const float*)d_in[13]; fsin=(const float*)d_in[14];
    } else {
        hidden=(const float*)d_in[0]; fcos=(const float*)d_in[1]; fsin=(const float*)d_in[2];
        wq_a=(const float*)d_in[4];   q_norm_w=(const float*)d_in[5];
        wq_b=(const float*)d_in[6];   wkv_a=(const float*)d_in[7];
        kv_norm_w=(const float*)d_in[8]; wkv_b=(const float*)d_in[9];
        wo=(const float*)d_in[10];    idx_wq_b=(const float*)d_in[11];
        idx_wk=(const float*)d_in[12]; idx_kn_w=(const float*)d_in[13];
        idx_kn_b=(const float*)d_in[14]; idx_wproj=(const float*)d_in[15];
    }

    float *qr,*q,*kvall,*kv,*kvp,*k,*qi,*ki,*wts,*iscore,*comb,*scores,*attnout;
    GSYM(qr,g_qr); GSYM(q,g_q); GSYM(kvall,g_kvall); GSYM(kv,g_kv); GSYM(kvp,g_kvp); GSYM(k,g_k);
    GSYM(qi,g_qi); GSYM(ki,g_ki); GSYM(wts,g_wts); GSYM(iscore,g_iscore);
    GSYM(comb,g_comb); GSYM(scores,g_scores); GSYM(attnout,g_attnout);
    bf16 *h_hi,*h_lo,*wqb_hi,*wqb_lo,*wkva_hi,*wkva_lo,*wkvb_hi,*wkvb_lo,*wo_hi,*wo_lo;
    bf16 *qrn_hi,*qrn_lo,*kvn_hi,*kvn_lo,*qh_hi,*qh_lo,*kh_hi,*kh_lo,*at_hi,*at_lo;
    bf16 *p_hi,*p_lo,*vT_hi,*vT_lo;
    GSYM(h_hi,g_h_hi); GSYM(h_lo,g_h_lo);
    GSYM(wqb_hi,g_wqb_hi); GSYM(wqb_lo,g_wqb_lo); GSYM(wkva_hi,g_wkva_hi); GSYM(wkva_lo,g_wkva_lo);
    GSYM(wkvb_hi,g_wkvb_hi); GSYM(wkvb_lo,g_wkvb_lo); GSYM(wo_hi,g_wo_hi); GSYM(wo_lo,g_wo_lo);
    GSYM(qrn_hi,g_qrn_hi); GSYM(qrn_lo,g_qrn_lo); GSYM(kvn_hi,g_kvn_hi); GSYM(kvn_lo,g_kvn_lo);
    GSYM(qh_hi,g_qh_hi); GSYM(qh_lo,g_qh_lo); GSYM(kh_hi,g_kh_hi); GSYM(kh_lo,g_kh_lo);
    GSYM(at_hi,g_at_hi); GSYM(at_lo,g_at_lo);
    GSYM(p_hi,g_p_hi); GSYM(p_lo,g_p_lo); GSYM(vT_hi,g_vT_hi); GSYM(vT_lo,g_vT_lo);
    float* outp = (float*)d_out;

    cudaFuncSetAttribute(gemm_mma_nt, cudaFuncAttributeMaxDynamicSharedMemorySize, MMA_SMEM);
    dim3 blk(16,16);
    const float inv_sqrt192 = 0.07216878364870323f;
    const float inv_sqrt32  = 0.17677669529663687f;

    // ---- indexer-critical chain: EXACT fp32 baseline numerics ----
    // fused qr + ki + wts (same A=hidden, K=2048; per-tile chain == baseline)
    gemm_qr_fused_k<<<dim3(14,16),blk>>>(hidden, wq_a, qr, idx_wk, ki, idx_wproj, wts, inv_sqrt32);
    rmsnorm_k<<<SQ,256>>>(qr,QRR, qr,QRR, q_norm_w,QRR);
    gemm_nt_k<<<dim3(32,16,1),blk>>>(qr,0,QRR, idx_wq_b,0,QRR, qi,0,4096, SQ,4096,QRR,1.f,0);
    rope_qi_k<<<SQ,1024>>>(qi,fcos,fsin);
    ln_rope_ki_k<<<SQ,128>>>(ki,idx_kn_w,idx_kn_b,fcos,fsin);
    indexer_k<<<dim3(SQ/64,SQ/128),blk>>>(qi,ki,wts,iscore);
    topk_mask_k<<<SQ,1024>>>(iscore,comb);

    // ---- smooth path: bf16x3 mma ----
    cvt(hidden,h_hi,h_lo,2048*2048);
    cvt(wkv_a,wkva_hi,wkva_lo,576*2048);
    cvt(wq_b,wqb_hi,wqb_lo,3072*1536);
    cvt(wkv_b,wkvb_hi,wkvb_lo,4096*512);
    cvt(wo,wo_hi,wo_lo,2048*2048);
    cvt(qr,qrn_hi,qrn_lo,2048*1536);

    gemm_mma_nt<<<dim3(5,16,1),256,MMA_SMEM>>>(h_hi,h_lo,0,2048, wkva_hi,wkva_lo,0,2048, kvall,0,576, 576,2048,1.f,0);
    rmsnorm_k<<<SQ,256>>>(kvall,576, kv,KRR, kv_norm_w,KRR);
    cvt(kv,kvn_hi,kvn_lo,2048*512);
    gemm_mma_nt<<<dim3(32,16,1),256,MMA_SMEM>>>(kvn_hi,kvn_lo,0,512, wkvb_hi,wkvb_lo,0,512, kvp,0,4096, 4096,512,1.f,0);
    gemm_mma_nt<<<dim3(24,16,1),256,MMA_SMEM>>>(qrn_hi,qrn_lo,0,1536, wqb_hi,wqb_lo,0,1536, q,0,3072, 3072,1536,1.f,0);
    rope_q_k<<<SQ,512>>>(q,fcos,fsin);
    build_k_k<<<dim3(SQ,NH),128>>>(kvp,kvall,k,fcos,fsin);
    cvt(q,qh_hi,qh_lo,2048*3072);
    cvt(k,kh_hi,kh_lo,2048*3072);
    gemm_mma_nt<<<dim3(16,16,16),256,MMA_SMEM>>>(qh_hi,qh_lo,192,3072, kh_hi,kh_lo,192,3072,
                                                 scores,(long)SQ*SQ,SQ, SQ,192,inv_sqrt192,1);
    softmax2_k<<<dim3(SQ,NH),256>>>(scores,comb,p_hi,p_lo);
    build_vT_k<<<dim3(8,128,16),256>>>(kvp, vT_hi, vT_lo);
    gemm_mma_nt<<<dim3(1,16,16),256,MMA_SMEM>>>(p_hi,p_lo,(long)SQ*SQ,SQ, vT_hi,vT_lo,(long)128*2048,2048,
                                                attnout,128,2048, 128,2048,1.f,2);
    cvt(attnout,at_hi,at_lo,2048*2048);
    gemm_mma_nt<<<dim3(16,16,1),256,MMA_SMEM>>>(at_hi,at_lo,0,2048, wo_hi,wo_lo,0,2048, outp,0,2048, 2048,2048,1.f,0);
}

// round 10
// speedup vs baseline: 1.2298x; 1.1315x over previous
#include <cuda_runtime.h>
#include <cuda_bf16.h>
#include <math.h>
#include <stdint.h>

#define SQ 2048
#define NH 16
#define QRR 1536
#define KRR 512
#define TOPK 512
#define DMM 2048
#define NEG_INF (__int_as_float(0xff800000))
typedef __nv_bfloat16 bf16;

// ---------------- fp32 scratch ----------------
__device__ float g_qr[SQ*QRR];
__device__ float g_q[SQ*NH*192];
__device__ float g_kvall[SQ*576];
__device__ float g_kv[SQ*KRR];
__device__ float g_kvp[SQ*NH*256];
__device__ float g_k[SQ*NH*192];
__device__ float g_qi[SQ*32*128];
__device__ float g_ki[SQ*128];
__device__ float g_wts[SQ*32];
__device__ float g_iscore[SQ*SQ];
__device__ float g_comb[SQ*SQ];
__device__ float g_scores[67108864];
__device__ float g_attnout[SQ*DMM];
// ---------------- bf16 hi/lo scratch (smooth path only) ----------------
__device__ bf16 g_h_hi[2048*2048],  g_h_lo[2048*2048];
__device__ bf16 g_wqb_hi[3072*1536],g_wqb_lo[3072*1536];
__device__ bf16 g_wkva_hi[576*2048],g_wkva_lo[576*2048];
__device__ bf16 g_wkvb_hi[4096*512],g_wkvb_lo[4096*512];
__device__ bf16 g_wo_hi[2048*2048], g_wo_lo[2048*2048];
__device__ bf16 g_qrn_hi[2048*1536],g_qrn_lo[2048*1536];
__device__ bf16 g_kvn_hi[2048*512], g_kvn_lo[2048*512];
__device__ bf16 g_qh_hi[2048*3072], g_qh_lo[2048*3072];
__device__ bf16 g_kh_hi[2048*3072], g_kh_lo[2048*3072];
__device__ bf16 g_at_hi[2048*2048], g_at_lo[2048*2048];
__device__ bf16 g_p_hi[67108864],   g_p_lo[67108864];
__device__ bf16 g_vT_hi[16*128*2048], g_vT_lo[16*128*2048];

// ================= mma.sync helpers =================
__device__ __forceinline__ uint32_t smem_u32(const void* p){
    uint32_t a; asm("{ .reg .u64 t; cvta.to.shared.u64 t, %1; cvt.u32.u64 %0, t; }":"=r"(a):"l"(p)); return a;
}
#define LDSM4(R, ADDR) asm volatile( \
    "ldmatrix.sync.aligned.m8n8.x4.shared.b16 {%0,%1,%2,%3}, [%4];" \
    : "=r"((R)[0]),"=r"((R)[1]),"=r"((R)[2]),"=r"((R)[3]) : "r"(ADDR))
#define MMA16816(D, A, B) asm volatile( \
    "mma.sync.aligned.m16n8k16.row.col.f32.bf16.bf16.f32 " \
    "{%0,%1,%2,%3}, {%4,%5,%6,%7}, {%8,%9}, {%0,%1,%2,%3};" \
    : "+f"((D)[0]),"+f"((D)[1]),"+f"((D)[2]),"+f"((D)[3]) \
    : "r"((A)[0]),"r"((A)[1]),"r"((A)[2]),"r"((A)[3]), "r"((B)[0]),"r"((B)[1]))

// ======= bf16x3 NT GEMM via mma.sync (smooth path) =======
// causal: 0=dense, 1=skip above-diagonal tiles, 2=K capped at m0+128 (PV)
#define LSTR 72
#define MMA_SMEM (4*128*LSTR*2)
__global__ __launch_bounds__(256) void gemm_mma_nt(
    const bf16* __restrict__ Ah, const bf16* __restrict__ Al, long sa, int lda,
    const bf16* __restrict__ Bh, const bf16* __restrict__ Bl, long sb, int ldb,
    float* __restrict__ C, long sc, int ldc, int N, int K, float alpha, int causal)
{
    int n0 = blockIdx.x*128, m0 = blockIdx.y*128;
    if (causal == 1 && n0 > m0+127) return;
    int Keff = K;
    if (causal == 2 && m0+128 < Keff) Keff = m0+128;
    Ah += (long)blockIdx.z*sa; Al += (long)blockIdx.z*sa;
    Bh += (long)blockIdx.z*sb; Bl += (long)blockIdx.z*sb;
    C  += (long)blockIdx.z*sc;

    extern __shared__ bf16 sm[];
    bf16 *sAh = sm, *sAl = sm + 128*LSTR, *sBh = sm + 2*128*LSTR, *sBl = sm + 3*128*LSTR;
    int tid = threadIdx.x, lane = tid & 31, wid = tid >> 5;
    int wm = (wid >> 1) * 32, wn = (wid & 1) * 64;
    float acc[2][8][4] = {};

    for (int kc = 0; kc < Keff; kc += 64){
        __syncthreads();
        #pragma unroll
        for (int it = 0; it < 4; it++){
            int c = tid + it*256, row = c >> 3, cb = (c & 7) * 8;
            long ga = (long)(m0+row)*lda + kc + cb;
            *(int4*)&sAh[row*LSTR + cb] = *(const int4*)(Ah + ga);
            *(int4*)&sAl[row*LSTR + cb] = *(const int4*)(Al + ga);
            int4 vh = make_int4(0,0,0,0), vl = vh;
            if (n0 + row < N){
                long gb = (long)(n0+row)*ldb + kc + cb;
                vh = *(const int4*)(Bh + gb); vl = *(const int4*)(Bl + gb);
            }
            *(int4*)&sBh[row*LSTR + cb] = vh;
            *(int4*)&sBl[row*LSTR + cb] = vl;
        }
        __syncthreads();

        int r = lane & 15, ko = (lane >> 4) * 8;
        #pragma unroll
        for (int ks = 0; ks < 4; ks++){
            uint32_t ah[2][4], al[2][4], bh[8][2], bl[8][2];
            #pragma unroll
            for (int mi = 0; mi < 2; mi++){
                uint32_t ad = smem_u32(&sAh[(wm + mi*16 + r)*LSTR + ks*16 + ko]);
                LDSM4(ah[mi], ad);
                ad = smem_u32(&sAl[(wm + mi*16 + r)*LSTR + ks*16 + ko]);
                LDSM4(al[mi], ad);
            }
            #pragma unroll
            for (int np = 0; np < 4; np++){
                uint32_t t4[4];
                uint32_t bd = smem_u32(&sBh[(wn + np*16 + r)*LSTR + ks*16 + ko]);
                LDSM4(t4, bd);
                bh[2*np][0]=t4[0]; bh[2*np][1]=t4[2]; bh[2*np+1][0]=t4[1]; bh[2*np+1][1]=t4[3];
                bd = smem_u32(&sBl[(wn + np*16 + r)*LSTR + ks*16 + ko]);
                LDSM4(t4, bd);
                bl[2*np][0]=t4[0]; bl[2*np][1]=t4[2]; bl[2*np+1][0]=t4[1]; bl[2*np+1][1]=t4[3];
            }
            #pragma unroll
            for (int mi = 0; mi < 2; mi++)
                #pragma unroll
                for (int ni = 0; ni < 8; ni++){
                    MMA16816(acc[mi][ni], ah[mi], bh[ni]);
                    MMA16816(acc[mi][ni], ah[mi], bl[ni]);
                    MMA16816(acc[mi][ni], al[mi], bh[ni]);
                }
        }
    }
    #pragma unroll
    for (int mi = 0; mi < 2; mi++){
        int mrow = m0 + wm + mi*16 + (lane >> 2);
        #pragma unroll
        for (int ni = 0; ni < 8; ni++){
            int n = n0 + wn + ni*8 + (lane & 3)*2;
            if (n < N){
                *(float2*)(C + (long)mrow*ldc + n)     = make_float2(alpha*acc[mi][ni][0], alpha*acc[mi][ni][1]);
                *(float2*)(C + (long)(mrow+8)*ldc + n) = make_float2(alpha*acc[mi][ni][2], alpha*acc[mi][ni][3]);
            }
        }
    }
}

// ======= fp32 SIMT NT GEMM core (bit-identical baseline) =======
__device__ __forceinline__ void gemm_core(
    const float* A, int lda, const float* B, int ldb,
    float* C, int ldc, int M, int N, int K, float alpha, int m0, int n0)
{
    __shared__ float As[2][16][128];
    __shared__ float Bs[2][16][128];
    int tx = threadIdx.x, ty = threadIdx.y, tid = ty*16+tx;
    int lrow = tid>>1, lcol = (tid&1)*8;
    const float* Ap = A + (long)(m0+lrow)*lda + lcol;
    const float* Bp = B + (long)(n0+lrow)*ldb + lcol;
    bool aval = (m0+lrow) < M, bval = (n0+lrow) < N;
    float4 ra0, ra1, rb0, rb1;
    const float4 z4 = make_float4(0.f,0.f,0.f,0.f);
    ra0 = aval ? *(const float4*)(Ap)   : z4;
    ra1 = aval ? *(const float4*)(Ap+4) : z4;
    rb0 = bval ? *(const float4*)(Bp)   : z4;
    rb1 = bval ? *(const float4*)(Bp+4) : z4;
    As[0][lcol+0][lrow]=ra0.x; As[0][lcol+1][lrow]=ra0.y; As[0][lcol+2][lrow]=ra0.z; As[0][lcol+3][lrow]=ra0.w;
    As[0][lcol+4][lrow]=ra1.x; As[0][lcol+5][lrow]=ra1.y; As[0][lcol+6][lrow]=ra1.z; As[0][lcol+7][lrow]=ra1.w;
    Bs[0][lcol+0][lrow]=rb0.x; Bs[0][lcol+1][lrow]=rb0.y; Bs[0][lcol+2][lrow]=rb0.z; Bs[0][lcol+3][lrow]=rb0.w;
    Bs[0][lcol+4][lrow]=rb1.x; Bs[0][lcol+5][lrow]=rb1.y; Bs[0][lcol+6][lrow]=rb1.z; Bs[0][lcol+7][lrow]=rb1.w;
    __syncthreads();
    float acc[8][8] = {};
    int nk = K>>4;
    for (int kt=0; kt<nk; kt++){
        int cur = kt&1;
        if (kt+1<nk){
            const float* Ap2 = Ap + (kt+1)*16;
            const float* Bp2 = Bp + (kt+1)*16;
            ra0 = aval ? *(const float4*)(Ap2)   : z4;
            ra1 = aval ? *(const float4*)(Ap2+4) : z4;
            rb0 = bval ? *(const float4*)(Bp2)   : z4;
            rb1 = bval ? *(const float4*)(Bp2+4) : z4;
        }
        #pragma unroll
        for (int k=0;k<16;k++){
            float4 a0=*(const float4*)(&As[cur][k][ty*8]);
            float4 a1=*(const float4*)(&As[cur][k][ty*8+4]);
            float4 b0=*(const float4*)(&Bs[cur][k][tx*8]);
            float4 b1=*(const float4*)(&Bs[cur][k][tx*8+4]);
            float a[8]={a0.x,a0.y,a0.z,a0.w,a1.x,a1.y,a1.z,a1.w};
            float b[8]={b0.x,b0.y,b0.z,b0.w,b1.x,b1.y,b1.z,b1.w};
            #pragma unroll
            for (int i=0;i<8;i++)
                #pragma unroll
                for (int j=0;j<8;j++) acc[i][j]+=a[i]*b[j];
        }
        if (kt+1<nk){
            int nx = cur^1;
            As[nx][lcol+0][lrow]=ra0.x; As[nx][lcol+1][lrow]=ra0.y; As[nx][lcol+2][lrow]=ra0.z; As[nx][lcol+3][lrow]=ra0.w;
            As[nx][lcol+4][lrow]=ra1.x; As[nx][lcol+5][lrow]=ra1.y; As[nx][lcol+6][lrow]=ra1.z; As[nx][lcol+7][lrow]=ra1.w;
            Bs[nx][lcol+0][lrow]=rb0.x; Bs[nx][lcol+1][lrow]=rb0.y; Bs[nx][lcol+2][lrow]=rb0.z; Bs[nx][lcol+3][lrow]=rb0.w;
            Bs[nx][lcol+4][lrow]=rb1.x; Bs[nx][lcol+5][lrow]=rb1.y; Bs[nx][lcol+6][lrow]=rb1.z; Bs[nx][lcol+7][lrow]=rb1.w;
        }
        __syncthreads();
    }
    #pragma unroll
    for (int i=0;i<8;i++){
        int m = m0+ty*8+i;
        if (m >= M) continue;
        int n = n0+tx*8;
        if (n < N){
            *(float4*)(C+(long)m*ldc+n)   = make_float4(acc[i][0]*alpha,acc[i][1]*alpha,acc[i][2]*alpha,acc[i][3]*alpha);
            *(float4*)(C+(long)m*ldc+n+4) = make_float4(acc[i][4]*alpha,acc[i][5]*alpha,acc[i][6]*alpha,acc[i][7]*alpha);
        }
    }
}

__global__ __launch_bounds__(256) void gemm_nt_k(
    const float* __restrict__ A, long sa, int lda,
    const float* __restrict__ B, long sb, int ldb,
    float* __restrict__ C, long sc, int ldc,
    int M, int N, int K, float alpha, int causal)
{
    int n0 = blockIdx.x*128, m0 = blockIdx.y*128;
    if (causal && n0 > m0+127) return;
    gemm_core(A + (long)blockIdx.z*sa, lda, B + (long)blockIdx.z*sb, ldb,
              C + (long)blockIdx.z*sc, ldc, M, N, K, alpha, m0, n0);
}

// fused qr+ki+wts (shared A=hidden, K=2048): tiles 0-11 -> qr, 12 -> ki, 13 -> wts
__global__ __launch_bounds__(256) void gemm_qr_fused_k(
    const float* __restrict__ hidden,
    const float* __restrict__ wq_a, float* __restrict__ qr,
    const float* __restrict__ idx_wk, float* __restrict__ ki,
    const float* __restrict__ idx_wproj, float* __restrict__ wts, float alpha2)
{
    int bx = blockIdx.x, m0 = blockIdx.y*128;
    if (bx < 12)      gemm_core(hidden, DMM, wq_a, DMM, qr, QRR, SQ, QRR, DMM, 1.f, m0, bx*128);
    else if (bx == 12) gemm_core(hidden, DMM, idx_wk, DMM, ki, 128, SQ, 128, DMM, 1.f, m0, 0);
    else               gemm_core(hidden, DMM, idx_wproj, DMM, wts, 32, SQ, 32, DMM, alpha2, m0, 0);
}

// ---------------- cvt / norms / ropes ----------------
__global__ void cvt_hilo_k(const float* __restrict__ in, bf16* __restrict__ hi, bf16* __restrict__ lo, int n){
    int i = blockIdx.x*256 + threadIdx.x;
    if (i < n){
        float x = in[i]; bf16 h = __float2bfloat16(x);
        hi[i] = h; lo[i] = __float2bfloat16(x - __bfloat162float(h));
    }
}
__global__ void rmsnorm_k(const float* __restrict__ in, int ldi,
                          float* __restrict__ out, int ldo,
                          const float* __restrict__ w, int D){
    int s = blockIdx.x, tid = threadIdx.x;
    __shared__ float red[256];
    const float* ip = in + (long)s*ldi;
    float ss = 0.f;
    for (int d=tid; d<D; d+=256){ float v = ip[d]; ss += v*v; }
    red[tid]=ss; __syncthreads();
    for (int o=128;o>0;o>>=1){ if(tid<o) red[tid]+=red[tid+o]; __syncthreads(); }
    float scale = rsqrtf(red[0]/(float)D + 1e-6f);
    float* op = out + (long)s*ldo;
    for (int d=tid; d<D; d+=256) op[d] = ip[d]*scale*w[d];
}
__global__ void rope_q_k(float* __restrict__ q, const float* __restrict__ cs, const float* __restrict__ sn){
    int s = blockIdx.x, tid = threadIdx.x, h = tid>>5, i = tid&31;
    float c = cs[s*32+i], si = sn[s*32+i];
    float* p = q + (long)s*3072 + h*192 + 128 + 2*i;
    float x0=p[0], x1=p[1]; p[0]=x0*c-x1*si; p[1]=x0*si+x1*c;
}
__global__ void build_k_k(const float* __restrict__ kvp, const float* __restrict__ kvall,
                          float* __restrict__ kk, const float* __restrict__ cs, const float* __restrict__ sn){
    int s = blockIdx.x, h = blockIdx.y, tid = threadIdx.x;
    float* dst = kk + ((long)s*16+h)*192;
    dst[tid] = kvp[(long)s*4096 + h*256 + tid];
    if (tid < 32){
        float c = cs[s*32+tid], si = sn[s*32+tid];
        float x0 = kvall[(long)s*576+512+2*tid], x1 = kvall[(long)s*576+513+2*tid];
        dst[128+2*tid]=x0*c-x1*si; dst[129+2*tid]=x0*si+x1*c;
    }
}
__global__ void rope_qi_k(float* __restrict__ qi, const float* __restrict__ cs, const float* __restrict__ sn){
    int s = blockIdx.x, tid = threadIdx.x, h = tid>>5, d = tid&31;
    float c = cs[s*32+d], si = sn[s*32+d];
    float* p = qi + (long)s*4096 + h*128;
    float x0=p[d], x1=p[d+32]; p[d]=x0*c-x1*si; p[d+32]=x0*si+x1*c;
}
__global__ void ln_rope_ki_k(float* __restrict__ ki, const float* __restrict__ w, const float* __restrict__ b,
                             const float* __restrict__ cs, const float* __restrict__ sn){
    int s = blockIdx.x, tid = threadIdx.x;
    __shared__ float red[128]; __shared__ float buf[128];
    float v = ki[(long)s*128+tid];
    red[tid]=v; __syncthreads();
    for (int o=64;o>0;o>>=1){ if(tid<o) red[tid]+=red[tid+o]; __syncthreads(); }
    float mean = red[0]/128.f; __syncthreads();
    float d = v-mean; red[tid]=d*d; __syncthreads();
    for (int o=64;o>0;o>>=1){ if(tid<o) red[tid]+=red[tid+o]; __syncthreads(); }
    float nv = d*rsqrtf(red[0]/128.f + 1e-5f)*w[tid] + b[tid];
    buf[tid]=nv; __syncthreads();
    float out;
    if (tid<32){ float c=cs[s*32+tid], si=sn[s*32+tid]; out = buf[tid]*c - buf[tid+32]*si; }
    else if (tid<64){ int i=tid-32; float c=cs[s*32+i], si=sn[s*32+i]; out = buf[i]*si + buf[i+32]*c; }
    else out = nv;
    ki[(long)s*128+tid] = out;
}
// ---------------- indexer (fp32 SIMT, baseline-identical) ----------------
__global__ __launch_bounds__(256) void indexer_k(
    const float* __restrict__ qi, const float* __restrict__ ki,
    const float* __restrict__ wts, float* __restrict__ out){
    int t0 = blockIdx.x*64, s0 = blockIdx.y*128;
    if (t0 > s0+127) return;
    __shared__ float Bs[128][64]; __shared__ float As[16][128]; __shared__ float Ws[128][16];
    int tx = threadIdx.x, ty = threadIdx.y, tid = ty*16+tx;
    {
        int t = tid>>2, kb = (tid&3)*32;
        const float* kp = ki + (long)(t0+t)*128 + kb;
        #pragma unroll
        for (int c=0; c<32; c+=4){
            float4 v = *(const float4*)(kp+c);
            Bs[kb+c][t]=v.x; Bs[kb+c+1][t]=v.y; Bs[kb+c+2][t]=v.z; Bs[kb+c+3][t]=v.w;
        }
    }
    const float scl = 0.08838834764831845f;
    float fin[8][4] = {};
    int arow = tid>>1, acol = (tid&1)*8;
    for (int hg=0; hg<2; hg++){
        __syncthreads();
        for (int i=tid; i<2048; i+=256)
            Ws[i>>4][i&15] = wts[(long)(s0+(i>>4))*32 + hg*16 + (i&15)];
        __syncthreads();
        for (int hh=0; hh<16; hh++){
            int h = hg*16+hh;
            float acc[8][4] = {};
            #pragma unroll
            for (int kc=0; kc<8; kc++){
                const float* qp = qi + (long)(s0+arow)*4096 + h*128 + kc*16 + acol;
                float4 v0 = *(const float4*)(qp), v1 = *(const float4*)(qp+4);
                __syncthreads();
                As[acol+0][arow]=v0.x; As[acol+1][arow]=v0.y; As[acol+2][arow]=v0.z; As[acol+3][arow]=v0.w;
                As[acol+4][arow]=v1.x; As[acol+5][arow]=v1.y; As[acol+6][arow]=v1.z; As[acol+7][arow]=v1.w;
                __syncthreads();
                #pragma unroll
                for (int k=0; k<16; k++){
                    float4 a0 = *(const float4*)(&As[k][ty*8]);
                    float4 a1 = *(const float4*)(&As[k][ty*8+4]);
                    float4 b4 = *(const float4*)(&Bs[kc*16+k][tx*4]);
                    float a[8]={a0.x,a0.y,a0.z,a0.w,a1.x,a1.y,a1.z,a1.w};
                    float b[4]={b4.x,b4.y,b4.z,b4.w};
                    #pragma unroll
                    for (int i=0;i<8;i++)
                        #pragma unroll
                        for (int j=0;j<4;j++) acc[i][j]+=a[i]*b[j];
                }
            }
            #pragma unroll
            for (int i=0;i<8;i++){
                float wv = Ws[ty*8+i][hh];
                #pragma unroll
                for (int j=0;j<4;j++) fin[i][j]+=fmaxf(acc[i][j]*scl,0.f)*wv;
            }
        }
    }
    #pragma unroll
    for (int i=0;i<8;i++){
        float4 o = make_float4(fin[i][0],fin[i][1],fin[i][2],fin[i][3]);
        *(float4*)(out + (long)(s0+ty*8+i)*SQ + t0 + tx*4) = o;
    }
}
// ---------------- top-512 -> combined mask ----------------
__global__ __launch_bounds__(1024) void topk_mask_k(const float* __restrict__ iscore, float* __restrict__ comb){
    int s = blockIdx.x, tid = threadIdx.x;
    __shared__ float sv[2048]; __shared__ float xo[2048];
    __shared__ unsigned char sel[2048]; __shared__ int s_cnt;
    for (int t=tid; t<2048; t+=1024){
        float v = (t<=s) ? iscore[(long)s*SQ+t] : NEG_INF;
        xo[t]=v; sv[t]=v; sel[t]=0;
    }
    if (tid==0) s_cnt=0;
    __syncthreads();
    if (s <= TOPK-1){
        for (int t=tid; t<2048; t+=1024) comb[(long)s*SQ+t] = (t<=s)?0.f:NEG_INF;
        return;
    }
    for (int k=2;k<=2048;k<<=1)
        for (int j=k>>1;j>0;j>>=1){
            for (int t=tid;t<2048;t+=1024){
                int ixj = t^j;
                if (ixj>t){
                    float a=sv[t], b=sv[ixj];
                    bool asc = ((t&k)==0);
                    if (asc ? (a>b):(a<b)){ sv[t]=b; sv[ixj]=a; }
                }
            }
            __syncthreads();
        }
    float T = sv[2048-TOPK];
    int local=0;
    for (int t=tid;t<=s;t+=1024) if (xo[t]>T){ sel[t]=1; local++; }
    atomicAdd(&s_cnt, local);
    __syncthreads();
    if (tid==0){
        int quota = TOPK - s_cnt;
        for (int t=0; t<=s && quota>0; t++) if (!sel[t] && xo[t]==T){ sel[t]=1; quota--; }
    }
    __syncthreads();
    for (int t=tid;t<2048;t+=1024) comb[(long)s*SQ+t] = sel[t]?0.f:NEG_INF;
}
// ---------------- masked softmax -> bf16 hi/lo probs, range-limited --------
__global__ void softmax2_k(const float* __restrict__ scores, const float* __restrict__ comb,
                           bf16* __restrict__ phi, bf16* __restrict__ plo){
    int s = blockIdx.x, h = blockIdx.y, tid = threadIdx.x;
    long ro = ((long)h*SQ+s)*SQ;
    const float* row = scores + ro;
    const float* cm = comb + (long)s*SQ;
    int lim = ((s>>7)+1)<<7;
    __shared__ float red[256];
    float m = NEG_INF;
    for (int t=tid;t<lim;t+=256) if (cm[t]==0.f) m = fmaxf(m, row[t]);
    red[tid]=m; __syncthreads();
    for (int o=128;o>0;o>>=1){ if(tid<o) red[tid]=fmaxf(red[tid],red[tid+o]); __syncthreads(); }
    m = red[0]; __syncthreads();
    float sum=0.f;
    for (int t=tid;t<lim;t+=256)
        if (cm[t]==0.f) sum += expf(row[t]-m);
    red[tid]=sum; __syncthreads();
    for (int o=128;o>0;o>>=1){ if(tid<o) red[tid]+=red[tid+o]; __syncthreads(); }
    float inv = 1.f/red[0];
    for (int t=tid;t<lim;t+=256){
        float p = (cm[t]==0.f) ? expf(row[t]-m)*inv : 0.f;
        bf16 hb = __float2bfloat16(p);
        phi[ro+t] = hb;
        plo[ro+t] = __float2bfloat16(p - __bfloat162float(hb));
    }
}
// ---------------- v^T build: kvp -> vT[h][n][k] bf16 hi/lo -----------------
__global__ void build_vT_k(const float* __restrict__ kvp, bf16* __restrict__ vhi, bf16* __restrict__ vlo){
    int s = blockIdx.x*256 + threadIdx.x;
    int n = blockIdx.y, h = blockIdx.z;
    float v = kvp[(long)s*4096 + h*256 + 128 + n];
    long o = ((long)h*128 + n)*2048 + s;
    bf16 hb = __float2bfloat16(v);
    vhi[o] = hb; vlo[o] = __float2bfloat16(v - __bfloat162float(hb));
}

// ================= host =================
static void cvtS(cudaStream_t st, const float* in, bf16* hi, bf16* lo, int n){
    cvt_hilo_k<<<(n+255)/256, 256, 0, st>>>(in, hi, lo, n);
}
#define GSYM(p, s) cudaGetSymbolAddress((void**)&p, s)

extern "C" void kernel_launch(void* const* d_in, const int* in_sizes, int n_in,
                              void* d_out, int out_size)
{
    if (n_in < 16) return;
    const float *hidden,*wq_a,*q_norm_w,*wq_b,*wkv_a,*kv_norm_w,*wkv_b,*wo;
    const float *idx_wq_b,*idx_wk,*idx_kn_w,*idx_kn_b,*idx_wproj,*fcos,*fsin;
    if (in_sizes[1] == 1536*2048){
        hidden=(const float*)d_in[0];  wq_a=(const float*)d_in[1];
        q_norm_w=(const float*)d_in[2]; wq_b=(const float*)d_in[3];
        wkv_a=(const float*)d_in[4];   kv_norm_w=(const float*)d_in[5];
        wkv_b=(const float*)d_in[6];   wo=(const float*)d_in[7];
        idx_wq_b=(const float*)d_in[8]; idx_wk=(const float*)d_in[9];
        idx_kn_w=(const float*)d_in[10]; idx_kn_b=(const float*)d_in[11];
        idx_wproj=(const float*)d_in[12]; fcos=(const float*)d_in[13]; fsin=(const float*)d_in[14];
    } else {
        hidden=(const float*)d_in[0]; fcos=(const float*)d_in[1]; fsin=(const float*)d_in[2];
        wq_a=(const float*)d_in[4];   q_norm_w=(const float*)d_in[5];
        wq_b=(const float*)d_in[6];   wkv_a=(const float*)d_in[7];
        kv_norm_w=(const float*)d_in[8]; wkv_b=(const float*)d_in[9];
        wo=(const float*)d_in[10];    idx_wq_b=(const float*)d_in[11];
        idx_wk=(const float*)d_in[12]; idx_kn_w=(const float*)d_in[13];
        idx_kn_b=(const float*)d_in[14]; idx_wproj=(const float*)d_in[15];
    }

    float *qr,*q,*kvall,*kv,*kvp,*k,*qi,*ki,*wts,*iscore,*comb,*scores,*attnout;
    GSYM(qr,g_qr); GSYM(q,g_q); GSYM(kvall,g_kvall); GSYM(kv,g_kv); GSYM(kvp,g_kvp); GSYM(k,g_k);
    GSYM(qi,g_qi); GSYM(ki,g_ki); GSYM(wts,g_wts); GSYM(iscore,g_iscore);
    GSYM(comb,g_comb); GSYM(scores,g_scores); GSYM(attnout,g_attnout);
    bf16 *h_hi,*h_lo,*wqb_hi,*wqb_lo,*wkva_hi,*wkva_lo,*wkvb_hi,*wkvb_lo,*wo_hi,*wo_lo;
    bf16 *qrn_hi,*qrn_lo,*kvn_hi,*kvn_lo,*qh_hi,*qh_lo,*kh_hi,*kh_lo,*at_hi,*at_lo;
    bf16 *p_hi,*p_lo,*vT_hi,*vT_lo;
    GSYM(h_hi,g_h_hi); GSYM(h_lo,g_h_lo);
    GSYM(wqb_hi,g_wqb_hi); GSYM(wqb_lo,g_wqb_lo); GSYM(wkva_hi,g_wkva_hi); GSYM(wkva_lo,g_wkva_lo);
    GSYM(wkvb_hi,g_wkvb_hi); GSYM(wkvb_lo,g_wkvb_lo); GSYM(wo_hi,g_wo_hi); GSYM(wo_lo,g_wo_lo);
    GSYM(qrn_hi,g_qrn_hi); GSYM(qrn_lo,g_qrn_lo); GSYM(kvn_hi,g_kvn_hi); GSYM(kvn_lo,g_kvn_lo);
    GSYM(qh_hi,g_qh_hi); GSYM(qh_lo,g_qh_lo); GSYM(kh_hi,g_kh_hi); GSYM(kh_lo,g_kh_lo);
    GSYM(at_hi,g_at_hi); GSYM(at_lo,g_at_lo);
    GSYM(p_hi,g_p_hi); GSYM(p_lo,g_p_lo); GSYM(vT_hi,g_vT_hi); GSYM(vT_lo,g_vT_lo);
    float* outp = (float*)d_out;

    // lazy stream/event creation (first call is the uncaptured correctness run)
    static cudaStream_t sB = 0;
    static cudaEvent_t evStart = 0, evQr = 0, evB = 0;
    if (!sB){
        cudaStreamCreateWithFlags(&sB, cudaStreamNonBlocking);
        cudaEventCreateWithFlags(&evStart, cudaEventDisableTiming);
        cudaEventCreateWithFlags(&evQr, cudaEventDisableTiming);
        cudaEventCreateWithFlags(&evB, cudaEventDisableTiming);
        cudaFuncSetAttribute(gemm_mma_nt, cudaFuncAttributeMaxDynamicSharedMemorySize, MMA_SMEM);
    }

    dim3 blk(16,16);
    const float inv_sqrt192 = 0.07216878364870323f;
    const float inv_sqrt32  = 0.17677669529663687f;

    // ---- fork ----
    cudaEventRecord(evStart, 0);
    cudaStreamWaitEvent(sB, evStart, 0);

    // ---- stream B (smooth path, part 1: independent of qr) ----
    cvtS(sB, hidden,h_hi,h_lo,2048*2048);
    cvtS(sB, wkv_a,wkva_hi,wkva_lo,576*2048);
    cvtS(sB, wq_b,wqb_hi,wqb_lo,3072*1536);
    cvtS(sB, wkv_b,wkvb_hi,wkvb_lo,4096*512);
    cvtS(sB, wo,wo_hi,wo_lo,2048*2048);
    gemm_mma_nt<<<dim3(5,16,1),256,MMA_SMEM,sB>>>(h_hi,h_lo,0,2048, wkva_hi,wkva_lo,0,2048, kvall,0,576, 576,2048,1.f,0);
    rmsnorm_k<<<SQ,256,0,sB>>>(kvall,576, kv,KRR, kv_norm_w,KRR);
    cvtS(sB, kv,kvn_hi,kvn_lo,2048*512);
    gemm_mma_nt<<<dim3(32,16,1),256,MMA_SMEM,sB>>>(kvn_hi,kvn_lo,0,512, wkvb_hi,wkvb_lo,0,512, kvp,0,4096, 4096,512,1.f,0);

    // ---- stream A (default): indexer-critical chain, EXACT fp32 baseline --
    gemm_qr_fused_k<<<dim3(14,16),blk>>>(hidden, wq_a, qr, idx_wk, ki, idx_wproj, wts, inv_sqrt32);
    rmsnorm_k<<<SQ,256>>>(qr,QRR, qr,QRR, q_norm_w,QRR);
    cudaEventRecord(evQr, 0);

    // ---- stream B (part 2: needs normed qr) ----
    cudaStreamWaitEvent(sB, evQr, 0);
    cvtS(sB, qr,qrn_hi,qrn_lo,2048*1536);
    gemm_mma_nt<<<dim3(24,16,1),256,MMA_SMEM,sB>>>(qrn_hi,qrn_lo,0,1536, wqb_hi,wqb_lo,0,1536, q,0,3072, 3072,1536,1.f,0);
    rope_q_k<<<SQ,512,0,sB>>>(q,fcos,fsin);
    build_k_k<<<dim3(SQ,NH),128,0,sB>>>(kvp,kvall,k,fcos,fsin);
    cvtS(sB, q,qh_hi,qh_lo,2048*3072);
    cvtS(sB, k,kh_hi,kh_lo,2048*3072);
    gemm_mma_nt<<<dim3(16,16,16),256,MMA_SMEM,sB>>>(qh_hi,qh_lo,192,3072, kh_hi,kh_lo,192,3072,
                                                    scores,(long)SQ*SQ,SQ, SQ,192,inv_sqrt192,1);
    build_vT_k<<<dim3(8,128,16),256,0,sB>>>(kvp, vT_hi, vT_lo);
    cudaEventRecord(evB, sB);

    // ---- stream A continues: qi -> indexer -> topk ----
    gemm_nt_k<<<dim3(32,16,1),blk>>>(qr,0,QRR, idx_wq_b,0,QRR, qi,0,4096, SQ,4096,QRR,1.f,0);
    rope_qi_k<<<SQ,1024>>>(qi,fcos,fsin);
    ln_rope_ki_k<<<SQ,128>>>(ki,idx_kn_w,idx_kn_b,fcos,fsin);
    indexer_k<<<dim3(SQ/64,SQ/128),blk>>>(qi,ki,wts,iscore);
    topk_mask_k<<<SQ,1024>>>(iscore,comb);

    // ---- join + tail on default stream ----
    cudaStreamWaitEvent(0, evB, 0);
    softmax2_k<<<dim3(SQ,NH),256>>>(scores,comb,p_hi,p_lo);
    gemm_mma_nt<<<dim3(1,16,16),256,MMA_SMEM>>>(p_hi,p_lo,(long)SQ*SQ,SQ, vT_hi,vT_lo,(long)128*2048,2048,
                                                attnout,128,2048, 128,2048,1.f,2);
    cvtS(0, attnout,at_hi,at_lo,2048*2048);
    gemm_mma_nt<<<dim3(16,16,1),256,MMA_SMEM>>>(at_hi,at_lo,0,2048, wo_hi,wo_lo,0,2048, outp,0,2048, 2048,2048,1.f,0);
}

// round 11
// speedup vs baseline: 1.3159x; 1.0700x over previous
#include <cuda_runtime.h>
#include <cuda_bf16.h>
#include <math.h>
#include <stdint.h>

#define SQ 2048
#define NH 16
#define QRR 1536
#define KRR 512
#define TOPK 512
#define DMM 2048
#define NEG_INF (__int_as_float(0xff800000))
typedef __nv_bfloat16 bf16;

// ---------------- fp32 scratch ----------------
__device__ float g_qr[SQ*QRR];
__device__ float g_q[SQ*NH*192];
__device__ float g_kvall[SQ*576];
__device__ float g_kv[SQ*KRR];
__device__ float g_kvp[SQ*NH*256];
__device__ float g_k[SQ*NH*192];
__device__ float g_qi[SQ*32*128];
__device__ float g_ki[SQ*128];
__device__ float g_wts[SQ*32];
__device__ float g_iscore[SQ*SQ];
__device__ float g_comb[SQ*SQ];
__device__ float g_scores[67108864];
__device__ float g_attnout[SQ*DMM];
// ---------------- bf16 hi/lo scratch (smooth path only) ----------------
__device__ bf16 g_h_hi[2048*2048],  g_h_lo[2048*2048];
__device__ bf16 g_wqb_hi[3072*1536],g_wqb_lo[3072*1536];
__device__ bf16 g_wkva_hi[576*2048],g_wkva_lo[576*2048];
__device__ bf16 g_wkvb_hi[4096*512],g_wkvb_lo[4096*512];
__device__ bf16 g_wo_hi[2048*2048], g_wo_lo[2048*2048];
__device__ bf16 g_qrn_hi[2048*1536],g_qrn_lo[2048*1536];
__device__ bf16 g_kvn_hi[2048*512], g_kvn_lo[2048*512];
__device__ bf16 g_qh_hi[2048*3072], g_qh_lo[2048*3072];
__device__ bf16 g_kh_hi[2048*3072], g_kh_lo[2048*3072];
__device__ bf16 g_at_hi[2048*2048], g_at_lo[2048*2048];
__device__ bf16 g_p_hi[67108864],   g_p_lo[67108864];
__device__ bf16 g_vT_hi[16*128*2048], g_vT_lo[16*128*2048];

// ================= mma.sync helpers =================
__device__ __forceinline__ uint32_t smem_u32(const void* p){
    uint32_t a; asm("{ .reg .u64 t; cvta.to.shared.u64 t, %1; cvt.u32.u64 %0, t; }":"=r"(a):"l"(p)); return a;
}
#define LDSM4(R, ADDR) asm volatile( \
    "ldmatrix.sync.aligned.m8n8.x4.shared.b16 {%0,%1,%2,%3}, [%4];" \
    : "=r"((R)[0]),"=r"((R)[1]),"=r"((R)[2]),"=r"((R)[3]) : "r"(ADDR))
#define MMA16816(D, A, B) asm volatile( \
    "mma.sync.aligned.m16n8k16.row.col.f32.bf16.bf16.f32 " \
    "{%0,%1,%2,%3}, {%4,%5,%6,%7}, {%8,%9}, {%0,%1,%2,%3};" \
    : "+f"((D)[0]),"+f"((D)[1]),"+f"((D)[2]),"+f"((D)[3]) \
    : "r"((A)[0]),"r"((A)[1]),"r"((A)[2]),"r"((A)[3]), "r"((B)[0]),"r"((B)[1]))

// ======= bf16x3 NT GEMM via mma.sync (smooth path) =======
// causal: 0=dense, 1=skip above-diagonal tiles, 2=K capped at m0+128 (PV)
#define LSTR 72
#define MMA_SMEM (4*128*LSTR*2)
__global__ __launch_bounds__(256) void gemm_mma_nt(
    const bf16* __restrict__ Ah, const bf16* __restrict__ Al, long sa, int lda,
    const bf16* __restrict__ Bh, const bf16* __restrict__ Bl, long sb, int ldb,
    float* __restrict__ C, long sc, int ldc, int N, int K, float alpha, int causal)
{
    int n0 = blockIdx.x*128, m0 = blockIdx.y*128;
    if (causal == 1 && n0 > m0+127) return;
    int Keff = K;
    if (causal == 2 && m0+128 < Keff) Keff = m0+128;
    Ah += (long)blockIdx.z*sa; Al += (long)blockIdx.z*sa;
    Bh += (long)blockIdx.z*sb; Bl += (long)blockIdx.z*sb;
    C  += (long)blockIdx.z*sc;

    extern __shared__ bf16 sm[];
    bf16 *sAh = sm, *sAl = sm + 128*LSTR, *sBh = sm + 2*128*LSTR, *sBl = sm + 3*128*LSTR;
    int tid = threadIdx.x, lane = tid & 31, wid = tid >> 5;
    int wm = (wid >> 1) * 32, wn = (wid & 1) * 64;
    float acc[2][8][4] = {};

    for (int kc = 0; kc < Keff; kc += 64){
        __syncthreads();
        #pragma unroll
        for (int it = 0; it < 4; it++){
            int c = tid + it*256, row = c >> 3, cb = (c & 7) * 8;
            long ga = (long)(m0+row)*lda + kc + cb;
            *(int4*)&sAh[row*LSTR + cb] = *(const int4*)(Ah + ga);
            *(int4*)&sAl[row*LSTR + cb] = *(const int4*)(Al + ga);
            int4 vh = make_int4(0,0,0,0), vl = vh;
            if (n0 + row < N){
                long gb = (long)(n0+row)*ldb + kc + cb;
                vh = *(const int4*)(Bh + gb); vl = *(const int4*)(Bl + gb);
            }
            *(int4*)&sBh[row*LSTR + cb] = vh;
            *(int4*)&sBl[row*LSTR + cb] = vl;
        }
        __syncthreads();

        int r = lane & 15, ko = (lane >> 4) * 8;
        #pragma unroll
        for (int ks = 0; ks < 4; ks++){
            uint32_t ah[2][4], al[2][4], bh[8][2], bl[8][2];
            #pragma unroll
            for (int mi = 0; mi < 2; mi++){
                uint32_t ad = smem_u32(&sAh[(wm + mi*16 + r)*LSTR + ks*16 + ko]);
                LDSM4(ah[mi], ad);
                ad = smem_u32(&sAl[(wm + mi*16 + r)*LSTR + ks*16 + ko]);
                LDSM4(al[mi], ad);
            }
            #pragma unroll
            for (int np = 0; np < 4; np++){
                uint32_t t4[4];
                uint32_t bd = smem_u32(&sBh[(wn + np*16 + r)*LSTR + ks*16 + ko]);
                LDSM4(t4, bd);
                bh[2*np][0]=t4[0]; bh[2*np][1]=t4[2]; bh[2*np+1][0]=t4[1]; bh[2*np+1][1]=t4[3];
                bd = smem_u32(&sBl[(wn + np*16 + r)*LSTR + ks*16 + ko]);
                LDSM4(t4, bd);
                bl[2*np][0]=t4[0]; bl[2*np][1]=t4[2]; bl[2*np+1][0]=t4[1]; bl[2*np+1][1]=t4[3];
            }
            #pragma unroll
            for (int mi = 0; mi < 2; mi++)
                #pragma unroll
                for (int ni = 0; ni < 8; ni++){
                    MMA16816(acc[mi][ni], ah[mi], bh[ni]);
                    MMA16816(acc[mi][ni], ah[mi], bl[ni]);
                    MMA16816(acc[mi][ni], al[mi], bh[ni]);
                }
        }
    }
    #pragma unroll
    for (int mi = 0; mi < 2; mi++){
        int mrow = m0 + wm + mi*16 + (lane >> 2);
        #pragma unroll
        for (int ni = 0; ni < 8; ni++){
            int n = n0 + wn + ni*8 + (lane & 3)*2;
            if (n < N){
                *(float2*)(C + (long)mrow*ldc + n)     = make_float2(alpha*acc[mi][ni][0], alpha*acc[mi][ni][1]);
                *(float2*)(C + (long)(mrow+8)*ldc + n) = make_float2(alpha*acc[mi][ni][2], alpha*acc[mi][ni][3]);
            }
        }
    }
}

// ======= fp32 SIMT NT GEMM core (bit-identical baseline) =======
__device__ __forceinline__ void gemm_core(
    const float* A, int lda, const float* B, int ldb,
    float* C, int ldc, int M, int N, int K, float alpha, int m0, int n0)
{
    __shared__ float As[2][16][128];
    __shared__ float Bs[2][16][128];
    int tx = threadIdx.x, ty = threadIdx.y, tid = ty*16+tx;
    int lrow = tid>>1, lcol = (tid&1)*8;
    const float* Ap = A + (long)(m0+lrow)*lda + lcol;
    const float* Bp = B + (long)(n0+lrow)*ldb + lcol;
    bool aval = (m0+lrow) < M, bval = (n0+lrow) < N;
    float4 ra0, ra1, rb0, rb1;
    const float4 z4 = make_float4(0.f,0.f,0.f,0.f);
    ra0 = aval ? *(const float4*)(Ap)   : z4;
    ra1 = aval ? *(const float4*)(Ap+4) : z4;
    rb0 = bval ? *(const float4*)(Bp)   : z4;
    rb1 = bval ? *(const float4*)(Bp+4) : z4;
    As[0][lcol+0][lrow]=ra0.x; As[0][lcol+1][lrow]=ra0.y; As[0][lcol+2][lrow]=ra0.z; As[0][lcol+3][lrow]=ra0.w;
    As[0][lcol+4][lrow]=ra1.x; As[0][lcol+5][lrow]=ra1.y; As[0][lcol+6][lrow]=ra1.z; As[0][lcol+7][lrow]=ra1.w;
    Bs[0][lcol+0][lrow]=rb0.x; Bs[0][lcol+1][lrow]=rb0.y; Bs[0][lcol+2][lrow]=rb0.z; Bs[0][lcol+3][lrow]=rb0.w;
    Bs[0][lcol+4][lrow]=rb1.x; Bs[0][lcol+5][lrow]=rb1.y; Bs[0][lcol+6][lrow]=rb1.z; Bs[0][lcol+7][lrow]=rb1.w;
    __syncthreads();
    float acc[8][8] = {};
    int nk = K>>4;
    for (int kt=0; kt<nk; kt++){
        int cur = kt&1;
        if (kt+1<nk){
            const float* Ap2 = Ap + (kt+1)*16;
            const float* Bp2 = Bp + (kt+1)*16;
            ra0 = aval ? *(const float4*)(Ap2)   : z4;
            ra1 = aval ? *(const float4*)(Ap2+4) : z4;
            rb0 = bval ? *(const float4*)(Bp2)   : z4;
            rb1 = bval ? *(const float4*)(Bp2+4) : z4;
        }
        #pragma unroll
        for (int k=0;k<16;k++){
            float4 a0=*(const float4*)(&As[cur][k][ty*8]);
            float4 a1=*(const float4*)(&As[cur][k][ty*8+4]);
            float4 b0=*(const float4*)(&Bs[cur][k][tx*8]);
            float4 b1=*(const float4*)(&Bs[cur][k][tx*8+4]);
            float a[8]={a0.x,a0.y,a0.z,a0.w,a1.x,a1.y,a1.z,a1.w};
            float b[8]={b0.x,b0.y,b0.z,b0.w,b1.x,b1.y,b1.z,b1.w};
            #pragma unroll
            for (int i=0;i<8;i++)
                #pragma unroll
                for (int j=0;j<8;j++) acc[i][j]+=a[i]*b[j];
        }
        if (kt+1<nk){
            int nx = cur^1;
            As[nx][lcol+0][lrow]=ra0.x; As[nx][lcol+1][lrow]=ra0.y; As[nx][lcol+2][lrow]=ra0.z; As[nx][lcol+3][lrow]=ra0.w;
            As[nx][lcol+4][lrow]=ra1.x; As[nx][lcol+5][lrow]=ra1.y; As[nx][lcol+6][lrow]=ra1.z; As[nx][lcol+7][lrow]=ra1.w;
            Bs[nx][lcol+0][lrow]=rb0.x; Bs[nx][lcol+1][lrow]=rb0.y; Bs[nx][lcol+2][lrow]=rb0.z; Bs[nx][lcol+3][lrow]=rb0.w;
            Bs[nx][lcol+4][lrow]=rb1.x; Bs[nx][lcol+5][lrow]=rb1.y; Bs[nx][lcol+6][lrow]=rb1.z; Bs[nx][lcol+7][lrow]=rb1.w;
        }
        __syncthreads();
    }
    #pragma unroll
    for (int i=0;i<8;i++){
        int m = m0+ty*8+i;
        if (m >= M) continue;
        int n = n0+tx*8;
        if (n < N){
            *(float4*)(C+(long)m*ldc+n)   = make_float4(acc[i][0]*alpha,acc[i][1]*alpha,acc[i][2]*alpha,acc[i][3]*alpha);
            *(float4*)(C+(long)m*ldc+n+4) = make_float4(acc[i][4]*alpha,acc[i][5]*alpha,acc[i][6]*alpha,acc[i][7]*alpha);
        }
    }
}

__global__ __launch_bounds__(256) void gemm_nt_k(
    const float* __restrict__ A, long sa, int lda,
    const float* __restrict__ B, long sb, int ldb,
    float* __restrict__ C, long sc, int ldc,
    int M, int N, int K, float alpha, int causal)
{
    int n0 = blockIdx.x*128, m0 = blockIdx.y*128;
    if (causal && n0 > m0+127) return;
    gemm_core(A + (long)blockIdx.z*sa, lda, B + (long)blockIdx.z*sb, ldb,
              C + (long)blockIdx.z*sc, ldc, M, N, K, alpha, m0, n0);
}

// fused qr+ki+wts (shared A=hidden, K=2048): tiles 0-11 -> qr, 12 -> ki, 13 -> wts
__global__ __launch_bounds__(256) void gemm_qr_fused_k(
    const float* __restrict__ hidden,
    const float* __restrict__ wq_a, float* __restrict__ qr,
    const float* __restrict__ idx_wk, float* __restrict__ ki,
    const float* __restrict__ idx_wproj, float* __restrict__ wts, float alpha2)
{
    int bx = blockIdx.x, m0 = blockIdx.y*128;
    if (bx < 12)      gemm_core(hidden, DMM, wq_a, DMM, qr, QRR, SQ, QRR, DMM, 1.f, m0, bx*128);
    else if (bx == 12) gemm_core(hidden, DMM, idx_wk, DMM, ki, 128, SQ, 128, DMM, 1.f, m0, 0);
    else               gemm_core(hidden, DMM, idx_wproj, DMM, wts, 32, SQ, 32, DMM, alpha2, m0, 0);
}

// ---------------- cvt / norms / ropes ----------------
__global__ void cvt_hilo_k(const float* __restrict__ in, bf16* __restrict__ hi, bf16* __restrict__ lo, int n){
    int i = blockIdx.x*256 + threadIdx.x;
    if (i < n){
        float x = in[i]; bf16 h = __float2bfloat16(x);
        hi[i] = h; lo[i] = __float2bfloat16(x - __bfloat162float(h));
    }
}
__global__ void rmsnorm_k(const float* __restrict__ in, int ldi,
                          float* __restrict__ out, int ldo,
                          const float* __restrict__ w, int D){
    int s = blockIdx.x, tid = threadIdx.x;
    __shared__ float red[256];
    const float* ip = in + (long)s*ldi;
    float ss = 0.f;
    for (int d=tid; d<D; d+=256){ float v = ip[d]; ss += v*v; }
    red[tid]=ss; __syncthreads();
    for (int o=128;o>0;o>>=1){ if(tid<o) red[tid]+=red[tid+o]; __syncthreads(); }
    float scale = rsqrtf(red[0]/(float)D + 1e-6f);
    float* op = out + (long)s*ldo;
    for (int d=tid; d<D; d+=256) op[d] = ip[d]*scale*w[d];
}
__global__ void rope_q_k(float* __restrict__ q, const float* __restrict__ cs, const float* __restrict__ sn){
    int s = blockIdx.x, tid = threadIdx.x, h = tid>>5, i = tid&31;
    float c = cs[s*32+i], si = sn[s*32+i];
    float* p = q + (long)s*3072 + h*192 + 128 + 2*i;
    float x0=p[0], x1=p[1]; p[0]=x0*c-x1*si; p[1]=x0*si+x1*c;
}
__global__ void build_k_k(const float* __restrict__ kvp, const float* __restrict__ kvall,
                          float* __restrict__ kk, const float* __restrict__ cs, const float* __restrict__ sn){
    int s = blockIdx.x, h = blockIdx.y, tid = threadIdx.x;
    float* dst = kk + ((long)s*16+h)*192;
    dst[tid] = kvp[(long)s*4096 + h*256 + tid];
    if (tid < 32){
        float c = cs[s*32+tid], si = sn[s*32+tid];
        float x0 = kvall[(long)s*576+512+2*tid], x1 = kvall[(long)s*576+513+2*tid];
        dst[128+2*tid]=x0*c-x1*si; dst[129+2*tid]=x0*si+x1*c;
    }
}
__global__ void rope_qi_k(float* __restrict__ qi, const float* __restrict__ cs, const float* __restrict__ sn){
    int s = blockIdx.x, tid = threadIdx.x, h = tid>>5, d = tid&31;
    float c = cs[s*32+d], si = sn[s*32+d];
    float* p = qi + (long)s*4096 + h*128;
    float x0=p[d], x1=p[d+32]; p[d]=x0*c-x1*si; p[d+32]=x0*si+x1*c;
}
__global__ void ln_rope_ki_k(float* __restrict__ ki, const float* __restrict__ w, const float* __restrict__ b,
                             const float* __restrict__ cs, const float* __restrict__ sn){
    int s = blockIdx.x, tid = threadIdx.x;
    __shared__ float red[128]; __shared__ float buf[128];
    float v = ki[(long)s*128+tid];
    red[tid]=v; __syncthreads();
    for (int o=64;o>0;o>>=1){ if(tid<o) red[tid]+=red[tid+o]; __syncthreads(); }
    float mean = red[0]/128.f; __syncthreads();
    float d = v-mean; red[tid]=d*d; __syncthreads();
    for (int o=64;o>0;o>>=1){ if(tid<o) red[tid]+=red[tid+o]; __syncthreads(); }
    float nv = d*rsqrtf(red[0]/128.f + 1e-5f)*w[tid] + b[tid];
    buf[tid]=nv; __syncthreads();
    float out;
    if (tid<32){ float c=cs[s*32+tid], si=sn[s*32+tid]; out = buf[tid]*c - buf[tid+32]*si; }
    else if (tid<64){ int i=tid-32; float c=cs[s*32+i], si=sn[s*32+i]; out = buf[i]*si + buf[i+32]*c; }
    else out = nv;
    ki[(long)s*128+tid] = out;
}
// ---------------- indexer (fp32 SIMT, baseline-identical) ----------------
__global__ __launch_bounds__(256) void indexer_k(
    const float* __restrict__ qi, const float* __restrict__ ki,
    const float* __restrict__ wts, float* __restrict__ out){
    int t0 = blockIdx.x*64, s0 = blockIdx.y*128;
    if (t0 > s0+127) return;
    __shared__ float Bs[128][64]; __shared__ float As[16][128]; __shared__ float Ws[128][16];
    int tx = threadIdx.x, ty = threadIdx.y, tid = ty*16+tx;
    {
        int t = tid>>2, kb = (tid&3)*32;
        const float* kp = ki + (long)(t0+t)*128 + kb;
        #pragma unroll
        for (int c=0; c<32; c+=4){
            float4 v = *(const float4*)(kp+c);
            Bs[kb+c][t]=v.x; Bs[kb+c+1][t]=v.y; Bs[kb+c+2][t]=v.z; Bs[kb+c+3][t]=v.w;
        }
    }
    const float scl = 0.08838834764831845f;
    float fin[8][4] = {};
    int arow = tid>>1, acol = (tid&1)*8;
    for (int hg=0; hg<2; hg++){
        __syncthreads();
        for (int i=tid; i<2048; i+=256)
            Ws[i>>4][i&15] = wts[(long)(s0+(i>>4))*32 + hg*16 + (i&15)];
        __syncthreads();
        for (int hh=0; hh<16; hh++){
            int h = hg*16+hh;
            float acc[8][4] = {};
            #pragma unroll
            for (int kc=0; kc<8; kc++){
                const float* qp = qi + (long)(s0+arow)*4096 + h*128 + kc*16 + acol;
                float4 v0 = *(const float4*)(qp), v1 = *(const float4*)(qp+4);
                __syncthreads();
                As[acol+0][arow]=v0.x; As[acol+1][arow]=v0.y; As[acol+2][arow]=v0.z; As[acol+3][arow]=v0.w;
                As[acol+4][arow]=v1.x; As[acol+5][arow]=v1.y; As[acol+6][arow]=v1.z; As[acol+7][arow]=v1.w;
                __syncthreads();
                #pragma unroll
                for (int k=0; k<16; k++){
                    float4 a0 = *(const float4*)(&As[k][ty*8]);
                    float4 a1 = *(const float4*)(&As[k][ty*8+4]);
                    float4 b4 = *(const float4*)(&Bs[kc*16+k][tx*4]);
                    float a[8]={a0.x,a0.y,a0.z,a0.w,a1.x,a1.y,a1.z,a1.w};
                    float b[4]={b4.x,b4.y,b4.z,b4.w};
                    #pragma unroll
                    for (int i=0;i<8;i++)
                        #pragma unroll
                        for (int j=0;j<4;j++) acc[i][j]+=a[i]*b[j];
                }
            }
            #pragma unroll
            for (int i=0;i<8;i++){
                float wv = Ws[ty*8+i][hh];
                #pragma unroll
                for (int j=0;j<4;j++) fin[i][j]+=fmaxf(acc[i][j]*scl,0.f)*wv;
            }
        }
    }
    #pragma unroll
    for (int i=0;i<8;i++){
        float4 o = make_float4(fin[i][0],fin[i][1],fin[i][2],fin[i][3]);
        *(float4*)(out + (long)(s0+ty*8+i)*SQ + t0 + tx*4) = o;
    }
}
// ---------------- top-512 via exact radix-select (comb bit-identical) ------
__device__ __forceinline__ uint32_t fmap(float f){
    uint32_t u = __float_as_uint(f);
    return (u & 0x80000000u) ? ~u : (u | 0x80000000u);
}
__global__ __launch_bounds__(256) void topk_mask_k(const float* __restrict__ iscore, float* __restrict__ comb){
    int s = blockIdx.x, tid = threadIdx.x;
    __shared__ float xo[2048];
    __shared__ unsigned char sel[2048];
    __shared__ int hist[256];
    __shared__ int sh_b, sh_K, s_cnt;
    for (int t=tid; t<2048; t+=256){
        xo[t] = (t<=s) ? iscore[(long)s*SQ+t] : NEG_INF;
        sel[t] = 0;
    }
    if (tid==0){ s_cnt=0; sh_K=TOPK; }
    __syncthreads();
    if (s <= TOPK-1){
        for (int t=tid; t<2048; t+=256) comb[(long)s*SQ+t] = (t<=s)?0.f:NEG_INF;
        return;
    }
    // 4-pass radix select of the 512th-largest mapped key (exact order statistic)
    uint32_t prefix = 0;
    for (int pass=0; pass<4; pass++){
        int shift = 24 - 8*pass;
        uint32_t maskHi = (pass==0) ? 0u : (0xFFFFFFFFu << (shift+8));
        hist[tid & 255] = 0;
        __syncthreads();
        for (int t=tid; t<=s; t+=256){
            uint32_t u = fmap(xo[t]);
            if ((u & maskHi) == prefix)
                atomicAdd(&hist[(u >> shift) & 255], 1);
        }
        __syncthreads();
        if (tid==0){
            int K = sh_K, cum = 0, b = 255;
            for (; b>=0; b--){
                int c = hist[b];
                if (cum + c >= K){ sh_b = b; sh_K = K - cum; break; }
                cum += c;
            }
        }
        __syncthreads();
        prefix |= ((uint32_t)sh_b) << shift;
        __syncthreads();
    }
    uint32_t mT = prefix;
    float T = (mT & 0x80000000u) ? __uint_as_float(mT ^ 0x80000000u) : __uint_as_float(~mT);
    // selection identical to baseline: > T, then ties at T by lowest index
    int local = 0;
    for (int t=tid; t<=s; t+=256)
        if (xo[t] > T){ sel[t] = 1; local++; }
    atomicAdd(&s_cnt, local);
    __syncthreads();
    if (tid==0){
        int quota = TOPK - s_cnt;
        for (int t=0; t<=s && quota>0; t++)
            if (!sel[t] && xo[t] == T){ sel[t]=1; quota--; }
    }
    __syncthreads();
    for (int t=tid; t<2048; t+=256)
        comb[(long)s*SQ+t] = sel[t] ? 0.f : NEG_INF;
}
// ---------------- masked softmax -> bf16 hi/lo probs, range-limited --------
__global__ void softmax2_k(const float* __restrict__ scores, const float* __restrict__ comb,
                           bf16* __restrict__ phi, bf16* __restrict__ plo){
    int s = blockIdx.x, h = blockIdx.y, tid = threadIdx.x;
    long ro = ((long)h*SQ+s)*SQ;
    const float* row = scores + ro;
    const float* cm = comb + (long)s*SQ;
    int lim = ((s>>7)+1)<<7;
    __shared__ float red[256];
    float m = NEG_INF;
    for (int t=tid;t<lim;t+=256) if (cm[t]==0.f) m = fmaxf(m, row[t]);
    red[tid]=m; __syncthreads();
    for (int o=128;o>0;o>>=1){ if(tid<o) red[tid]=fmaxf(red[tid],red[tid+o]); __syncthreads(); }
    m = red[0]; __syncthreads();
    float sum=0.f;
    for (int t=tid;t<lim;t+=256)
        if (cm[t]==0.f) sum += expf(row[t]-m);
    red[tid]=sum; __syncthreads();
    for (int o=128;o>0;o>>=1){ if(tid<o) red[tid]+=red[tid+o]; __syncthreads(); }
    float inv = 1.f/red[0];
    for (int t=tid;t<lim;t+=256){
        float p = (cm[t]==0.f) ? expf(row[t]-m)*inv : 0.f;
        bf16 hb = __float2bfloat16(p);
        phi[ro+t] = hb;
        plo[ro+t] = __float2bfloat16(p - __bfloat162float(hb));
    }
}
// ---------------- v^T build: kvp -> vT[h][n][k] bf16 hi/lo -----------------
__global__ void build_vT_k(const float* __restrict__ kvp, bf16* __restrict__ vhi, bf16* __restrict__ vlo){
    int s = blockIdx.x*256 + threadIdx.x;
    int n = blockIdx.y, h = blockIdx.z;
    float v = kvp[(long)s*4096 + h*256 + 128 + n];
    long o = ((long)h*128 + n)*2048 + s;
    bf16 hb = __float2bfloat16(v);
    vhi[o] = hb; vlo[o] = __float2bfloat16(v - __bfloat162float(hb));
}

// ================= host =================
static void cvtS(cudaStream_t st, const float* in, bf16* hi, bf16* lo, int n){
    cvt_hilo_k<<<(n+255)/256, 256, 0, st>>>(in, hi, lo, n);
}
#define GSYM(p, s) cudaGetSymbolAddress((void**)&p, s)

extern "C" void kernel_launch(void* const* d_in, const int* in_sizes, int n_in,
                              void* d_out, int out_size)
{
    if (n_in < 16) return;
    const float *hidden,*wq_a,*q_norm_w,*wq_b,*wkv_a,*kv_norm_w,*wkv_b,*wo;
    const float *idx_wq_b,*idx_wk,*idx_kn_w,*idx_kn_b,*idx_wproj,*fcos,*fsin;
    if (in_sizes[1] == 1536*2048){
        hidden=(const float*)d_in[0];  wq_a=(const float*)d_in[1];
        q_norm_w=(const float*)d_in[2]; wq_b=(const float*)d_in[3];
        wkv_a=(const float*)d_in[4];   kv_norm_w=(const float*)d_in[5];
        wkv_b=(const float*)d_in[6];   wo=(const float*)d_in[7];
        idx_wq_b=(const float*)d_in[8]; idx_wk=(const float*)d_in[9];
        idx_kn_w=(const float*)d_in[10]; idx_kn_b=(const float*)d_in[11];
        idx_wproj=(const float*)d_in[12]; fcos=(const float*)d_in[13]; fsin=(const float*)d_in[14];
    } else {
        hidden=(const float*)d_in[0]; fcos=(const float*)d_in[1]; fsin=(const float*)d_in[2];
        wq_a=(const float*)d_in[4];   q_norm_w=(const float*)d_in[5];
        wq_b=(const float*)d_in[6];   wkv_a=(const float*)d_in[7];
        kv_norm_w=(const float*)d_in[8]; wkv_b=(const float*)d_in[9];
        wo=(const float*)d_in[10];    idx_wq_b=(const float*)d_in[11];
        idx_wk=(const float*)d_in[12]; idx_kn_w=(const float*)d_in[13];
        idx_kn_b=(const float*)d_in[14]; idx_wproj=(const float*)d_in[15];
    }

    float *qr,*q,*kvall,*kv,*kvp,*k,*qi,*ki,*wts,*iscore,*comb,*scores,*attnout;
    GSYM(qr,g_qr); GSYM(q,g_q); GSYM(kvall,g_kvall); GSYM(kv,g_kv); GSYM(kvp,g_kvp); GSYM(k,g_k);
    GSYM(qi,g_qi); GSYM(ki,g_ki); GSYM(wts,g_wts); GSYM(iscore,g_iscore);
    GSYM(comb,g_comb); GSYM(scores,g_scores); GSYM(attnout,g_attnout);
    bf16 *h_hi,*h_lo,*wqb_hi,*wqb_lo,*wkva_hi,*wkva_lo,*wkvb_hi,*wkvb_lo,*wo_hi,*wo_lo;
    bf16 *qrn_hi,*qrn_lo,*kvn_hi,*kvn_lo,*qh_hi,*qh_lo,*kh_hi,*kh_lo,*at_hi,*at_lo;
    bf16 *p_hi,*p_lo,*vT_hi,*vT_lo;
    GSYM(h_hi,g_h_hi); GSYM(h_lo,g_h_lo);
    GSYM(wqb_hi,g_wqb_hi); GSYM(wqb_lo,g_wqb_lo); GSYM(wkva_hi,g_wkva_hi); GSYM(wkva_lo,g_wkva_lo);
    GSYM(wkvb_hi,g_wkvb_hi); GSYM(wkvb_lo,g_wkvb_lo); GSYM(wo_hi,g_wo_hi); GSYM(wo_lo,g_wo_lo);
    GSYM(qrn_hi,g_qrn_hi); GSYM(qrn_lo,g_qrn_lo); GSYM(kvn_hi,g_kvn_hi); GSYM(kvn_lo,g_kvn_lo);
    GSYM(qh_hi,g_qh_hi); GSYM(qh_lo,g_qh_lo); GSYM(kh_hi,g_kh_hi); GSYM(kh_lo,g_kh_lo);
    GSYM(at_hi,g_at_hi); GSYM(at_lo,g_at_lo);
    GSYM(p_hi,g_p_hi); GSYM(p_lo,g_p_lo); GSYM(vT_hi,g_vT_hi); GSYM(vT_lo,g_vT_lo);
    float* outp = (float*)d_out;

    static cudaStream_t sB = 0;
    static cudaEvent_t evStart = 0, evQr = 0, evB = 0;
    if (!sB){
        cudaStreamCreateWithFlags(&sB, cudaStreamNonBlocking);
        cudaEventCreateWithFlags(&evStart, cudaEventDisableTiming);
        cudaEventCreateWithFlags(&evQr, cudaEventDisableTiming);
        cudaEventCreateWithFlags(&evB, cudaEventDisableTiming);
        cudaFuncSetAttribute(gemm_mma_nt, cudaFuncAttributeMaxDynamicSharedMemorySize, MMA_SMEM);
    }

    dim3 blk(16,16);
    const float inv_sqrt192 = 0.07216878364870323f;
    const float inv_sqrt32  = 0.17677669529663687f;

    // ---- fork ----
    cudaEventRecord(evStart, 0);
    cudaStreamWaitEvent(sB, evStart, 0);

    // ---- stream B (smooth path, part 1: independent of qr) ----
    cvtS(sB, hidden,h_hi,h_lo,2048*2048);
    cvtS(sB, wkv_a,wkva_hi,wkva_lo,576*2048);
    cvtS(sB, wq_b,wqb_hi,wqb_lo,3072*1536);
    cvtS(sB, wkv_b,wkvb_hi,wkvb_lo,4096*512);
    cvtS(sB, wo,wo_hi,wo_lo,2048*2048);
    gemm_mma_nt<<<dim3(5,16,1),256,MMA_SMEM,sB>>>(h_hi,h_lo,0,2048, wkva_hi,wkva_lo,0,2048, kvall,0,576, 576,2048,1.f,0);
    rmsnorm_k<<<SQ,256,0,sB>>>(kvall,576, kv,KRR, kv_norm_w,KRR);
    cvtS(sB, kv,kvn_hi,kvn_lo,2048*512);
    gemm_mma_nt<<<dim3(32,16,1),256,MMA_SMEM,sB>>>(kvn_hi,kvn_lo,0,512, wkvb_hi,wkvb_lo,0,512, kvp,0,4096, 4096,512,1.f,0);
    // k-side work that needs only kvp/kvall — fill the bubble before qr is ready
    build_k_k<<<dim3(SQ,NH),128,0,sB>>>(kvp,kvall,k,fcos,fsin);
    build_vT_k<<<dim3(8,128,16),256,0,sB>>>(kvp, vT_hi, vT_lo);
    cvtS(sB, k,kh_hi,kh_lo,2048*3072);

    // ---- stream A (default): indexer-critical chain, EXACT fp32 baseline --
    gemm_qr_fused_k<<<dim3(14,16),blk>>>(hidden, wq_a, qr, idx_wk, ki, idx_wproj, wts, inv_sqrt32);
    rmsnorm_k<<<SQ,256>>>(qr,QRR, qr,QRR, q_norm_w,QRR);
    cudaEventRecord(evQr, 0);

    // ---- stream B (part 2: needs normed qr) ----
    cudaStreamWaitEvent(sB, evQr, 0);
    cvtS(sB, qr,qrn_hi,qrn_lo,2048*1536);
    gemm_mma_nt<<<dim3(24,16,1),256,MMA_SMEM,sB>>>(qrn_hi,qrn_lo,0,1536, wqb_hi,wqb_lo,0,1536, q,0,3072, 3072,1536,1.f,0);
    rope_q_k<<<SQ,512,0,sB>>>(q,fcos,fsin);
    cvtS(sB, q,qh_hi,qh_lo,2048*3072);
    gemm_mma_nt<<<dim3(16,16,16),256,MMA_SMEM,sB>>>(qh_hi,qh_lo,192,3072, kh_hi,kh_lo,192,3072,
                                                    scores,(long)SQ*SQ,SQ, SQ,192,inv_sqrt192,1);
    cudaEventRecord(evB, sB);

    // ---- stream A continues: qi -> indexer -> topk ----
    gemm_nt_k<<<dim3(32,16,1),blk>>>(qr,0,QRR, idx_wq_b,0,QRR, qi,0,4096, SQ,4096,QRR,1.f,0);
    rope_qi_k<<<SQ,1024>>>(qi,fcos,fsin);
    ln_rope_ki_k<<<SQ,128>>>(ki,idx_kn_w,idx_kn_b,fcos,fsin);
    indexer_k<<<dim3(SQ/64,SQ/128),blk>>>(qi,ki,wts,iscore);
    topk_mask_k<<<SQ,256>>>(iscore,comb);

    // ---- join + tail on default stream ----
    cudaStreamWaitEvent(0, evB, 0);
    softmax2_k<<<dim3(SQ,NH),256>>>(scores,comb,p_hi,p_lo);
    gemm_mma_nt<<<dim3(1,16,16),256,MMA_SMEM>>>(p_hi,p_lo,(long)SQ*SQ,SQ, vT_hi,vT_lo,(long)128*2048,2048,
                                                attnout,128,2048, 128,2048,1.f,2);
    cvtS(0, attnout,at_hi,at_lo,2048*2048);
    gemm_mma_nt<<<dim3(16,16,1),256,MMA_SMEM>>>(at_hi,at_lo,0,2048, wo_hi,wo_lo,0,2048, outp,0,2048, 2048,2048,1.f,0);
}

// round 12
// speedup vs baseline: 1.3315x; 1.0119x over previous
#include <cuda_runtime.h>
#include <cuda_bf16.h>
#include <math.h>
#include <stdint.h>

#define SQ 2048
#define NH 16
#define QRR 1536
#define KRR 512
#define TOPK 512
#define DMM 2048
#define NEG_INF (__int_as_float(0xff800000))
typedef __nv_bfloat16 bf16;

// ---------------- fp32 scratch ----------------
__device__ float g_qr[SQ*QRR];
__device__ float g_q[SQ*NH*192];
__device__ float g_kvall[SQ*576];
__device__ float g_kv[SQ*KRR];
__device__ float g_kvp[SQ*NH*256];
__device__ float g_k[SQ*NH*192];
__device__ float g_qi[SQ*32*128];
__device__ float g_ki[SQ*128];
__device__ float g_wts[SQ*32];
__device__ float g_iscore[SQ*SQ];
__device__ float g_comb[SQ*SQ];
__device__ float g_scores[67108864];
__device__ float g_attnout[SQ*DMM];
// ---------------- bf16 hi/lo scratch (smooth path only) ----------------
__device__ bf16 g_h_hi[2048*2048],  g_h_lo[2048*2048];
__device__ bf16 g_wqb_hi[3072*1536],g_wqb_lo[3072*1536];
__device__ bf16 g_wkva_hi[576*2048],g_wkva_lo[576*2048];
__device__ bf16 g_wkvb_hi[4096*512],g_wkvb_lo[4096*512];
__device__ bf16 g_wo_hi[2048*2048], g_wo_lo[2048*2048];
__device__ bf16 g_qrn_hi[2048*1536],g_qrn_lo[2048*1536];
__device__ bf16 g_kvn_hi[2048*512], g_kvn_lo[2048*512];
__device__ bf16 g_qh_hi[2048*3072], g_qh_lo[2048*3072];
__device__ bf16 g_kh_hi[2048*3072], g_kh_lo[2048*3072];
__device__ bf16 g_at_hi[2048*2048], g_at_lo[2048*2048];
__device__ bf16 g_p_hi[67108864],   g_p_lo[67108864];
__device__ bf16 g_vT_hi[16*128*2048], g_vT_lo[16*128*2048];

// ================= mma.sync helpers =================
__device__ __forceinline__ uint32_t smem_u32(const void* p){
    uint32_t a; asm("{ .reg .u64 t; cvta.to.shared.u64 t, %1; cvt.u32.u64 %0, t; }":"=r"(a):"l"(p)); return a;
}
#define LDSM4(R, ADDR) asm volatile( \
    "ldmatrix.sync.aligned.m8n8.x4.shared.b16 {%0,%1,%2,%3}, [%4];" \
    : "=r"((R)[0]),"=r"((R)[1]),"=r"((R)[2]),"=r"((R)[3]) : "r"(ADDR))
#define MMA16816(D, A, B) asm volatile( \
    "mma.sync.aligned.m16n8k16.row.col.f32.bf16.bf16.f32 " \
    "{%0,%1,%2,%3}, {%4,%5,%6,%7}, {%8,%9}, {%0,%1,%2,%3};" \
    : "+f"((D)[0]),"+f"((D)[1]),"+f"((D)[2]),"+f"((D)[3]) \
    : "r"((A)[0]),"r"((A)[1]),"r"((A)[2]),"r"((A)[3]), "r"((B)[0]),"r"((B)[1]))

// ======= bf16x3 NT GEMM via mma.sync (smooth path) =======
// causal: 0=dense, 1=skip above-diagonal tiles, 2=K capped at m0+128 (PV)
#define LSTR 72
#define MMA_SMEM (4*128*LSTR*2)
__global__ __launch_bounds__(256) void gemm_mma_nt(
    const bf16* __restrict__ Ah, const bf16* __restrict__ Al, long sa, int lda,
    const bf16* __restrict__ Bh, const bf16* __restrict__ Bl, long sb, int ldb,
    float* __restrict__ C, long sc, int ldc, int N, int K, float alpha, int causal)
{
    int n0 = blockIdx.x*128, m0 = blockIdx.y*128;
    if (causal == 1 && n0 > m0+127) return;
    int Keff = K;
    if (causal == 2 && m0+128 < Keff) Keff = m0+128;
    Ah += (long)blockIdx.z*sa; Al += (long)blockIdx.z*sa;
    Bh += (long)blockIdx.z*sb; Bl += (long)blockIdx.z*sb;
    C  += (long)blockIdx.z*sc;

    extern __shared__ bf16 sm[];
    bf16 *sAh = sm, *sAl = sm + 128*LSTR, *sBh = sm + 2*128*LSTR, *sBl = sm + 3*128*LSTR;
    int tid = threadIdx.x, lane = tid & 31, wid = tid >> 5;
    int wm = (wid >> 1) * 32, wn = (wid & 1) * 64;
    float acc[2][8][4] = {};

    for (int kc = 0; kc < Keff; kc += 64){
        __syncthreads();
        #pragma unroll
        for (int it = 0; it < 4; it++){
            int c = tid + it*256, row = c >> 3, cb = (c & 7) * 8;
            long ga = (long)(m0+row)*lda + kc + cb;
            *(int4*)&sAh[row*LSTR + cb] = *(const int4*)(Ah + ga);
            *(int4*)&sAl[row*LSTR + cb] = *(const int4*)(Al + ga);
            int4 vh = make_int4(0,0,0,0), vl = vh;
            if (n0 + row < N){
                long gb = (long)(n0+row)*ldb + kc + cb;
                vh = *(const int4*)(Bh + gb); vl = *(const int4*)(Bl + gb);
            }
            *(int4*)&sBh[row*LSTR + cb] = vh;
            *(int4*)&sBl[row*LSTR + cb] = vl;
        }
        __syncthreads();

        int r = lane & 15, ko = (lane >> 4) * 8;
        #pragma unroll
        for (int ks = 0; ks < 4; ks++){
            uint32_t ah[2][4], al[2][4], bh[8][2], bl[8][2];
            #pragma unroll
            for (int mi = 0; mi < 2; mi++){
                uint32_t ad = smem_u32(&sAh[(wm + mi*16 + r)*LSTR + ks*16 + ko]);
                LDSM4(ah[mi], ad);
                ad = smem_u32(&sAl[(wm + mi*16 + r)*LSTR + ks*16 + ko]);
                LDSM4(al[mi], ad);
            }
            #pragma unroll
            for (int np = 0; np < 4; np++){
                uint32_t t4[4];
                uint32_t bd = smem_u32(&sBh[(wn + np*16 + r)*LSTR + ks*16 + ko]);
                LDSM4(t4, bd);
                bh[2*np][0]=t4[0]; bh[2*np][1]=t4[2]; bh[2*np+1][0]=t4[1]; bh[2*np+1][1]=t4[3];
                bd = smem_u32(&sBl[(wn + np*16 + r)*LSTR + ks*16 + ko]);
                LDSM4(t4, bd);
                bl[2*np][0]=t4[0]; bl[2*np][1]=t4[2]; bl[2*np+1][0]=t4[1]; bl[2*np+1][1]=t4[3];
            }
            #pragma unroll
            for (int mi = 0; mi < 2; mi++)
                #pragma unroll
                for (int ni = 0; ni < 8; ni++){
                    MMA16816(acc[mi][ni], ah[mi], bh[ni]);
                    MMA16816(acc[mi][ni], ah[mi], bl[ni]);
                    MMA16816(acc[mi][ni], al[mi], bh[ni]);
                }
        }
    }
    #pragma unroll
    for (int mi = 0; mi < 2; mi++){
        int mrow = m0 + wm + mi*16 + (lane >> 2);
        #pragma unroll
        for (int ni = 0; ni < 8; ni++){
            int n = n0 + wn + ni*8 + (lane & 3)*2;
            if (n < N){
                *(float2*)(C + (long)mrow*ldc + n)     = make_float2(alpha*acc[mi][ni][0], alpha*acc[mi][ni][1]);
                *(float2*)(C + (long)(mrow+8)*ldc + n) = make_float2(alpha*acc[mi][ni][2], alpha*acc[mi][ni][3]);
            }
        }
    }
}

// ======= fp32 SIMT NT GEMM core (bit-identical baseline) =======
__device__ __forceinline__ void gemm_core(
    const float* A, int lda, const float* B, int ldb,
    float* C, int ldc, int M, int N, int K, float alpha, int m0, int n0)
{
    __shared__ float As[2][16][128];
    __shared__ float Bs[2][16][128];
    int tx = threadIdx.x, ty = threadIdx.y, tid = ty*16+tx;
    int lrow = tid>>1, lcol = (tid&1)*8;
    const float* Ap = A + (long)(m0+lrow)*lda + lcol;
    const float* Bp = B + (long)(n0+lrow)*ldb + lcol;
    bool aval = (m0+lrow) < M, bval = (n0+lrow) < N;
    float4 ra0, ra1, rb0, rb1;
    const float4 z4 = make_float4(0.f,0.f,0.f,0.f);
    ra0 = aval ? *(const float4*)(Ap)   : z4;
    ra1 = aval ? *(const float4*)(Ap+4) : z4;
    rb0 = bval ? *(const float4*)(Bp)   : z4;
    rb1 = bval ? *(const float4*)(Bp+4) : z4;
    As[0][lcol+0][lrow]=ra0.x; As[0][lcol+1][lrow]=ra0.y; As[0][lcol+2][lrow]=ra0.z; As[0][lcol+3][lrow]=ra0.w;
    As[0][lcol+4][lrow]=ra1.x; As[0][lcol+5][lrow]=ra1.y; As[0][lcol+6][lrow]=ra1.z; As[0][lcol+7][lrow]=ra1.w;
    Bs[0][lcol+0][lrow]=rb0.x; Bs[0][lcol+1][lrow]=rb0.y; Bs[0][lcol+2][lrow]=rb0.z; Bs[0][lcol+3][lrow]=rb0.w;
    Bs[0][lcol+4][lrow]=rb1.x; Bs[0][lcol+5][lrow]=rb1.y; Bs[0][lcol+6][lrow]=rb1.z; Bs[0][lcol+7][lrow]=rb1.w;
    __syncthreads();
    float acc[8][8] = {};
    int nk = K>>4;
    for (int kt=0; kt<nk; kt++){
        int cur = kt&1;
        if (kt+1<nk){
            const float* Ap2 = Ap + (kt+1)*16;
            const float* Bp2 = Bp + (kt+1)*16;
            ra0 = aval ? *(const float4*)(Ap2)   : z4;
            ra1 = aval ? *(const float4*)(Ap2+4) : z4;
            rb0 = bval ? *(const float4*)(Bp2)   : z4;
            rb1 = bval ? *(const float4*)(Bp2+4) : z4;
        }
        #pragma unroll
        for (int k=0;k<16;k++){
            float4 a0=*(const float4*)(&As[cur][k][ty*8]);
            float4 a1=*(const float4*)(&As[cur][k][ty*8+4]);
            float4 b0=*(const float4*)(&Bs[cur][k][tx*8]);
            float4 b1=*(const float4*)(&Bs[cur][k][tx*8+4]);
            float a[8]={a0.x,a0.y,a0.z,a0.w,a1.x,a1.y,a1.z,a1.w};
            float b[8]={b0.x,b0.y,b0.z,b0.w,b1.x,b1.y,b1.z,b1.w};
            #pragma unroll
            for (int i=0;i<8;i++)
                #pragma unroll
                for (int j=0;j<8;j++) acc[i][j]+=a[i]*b[j];
        }
        if (kt+1<nk){
            int nx = cur^1;
            As[nx][lcol+0][lrow]=ra0.x; As[nx][lcol+1][lrow]=ra0.y; As[nx][lcol+2][lrow]=ra0.z; As[nx][lcol+3][lrow]=ra0.w;
            As[nx][lcol+4][lrow]=ra1.x; As[nx][lcol+5][lrow]=ra1.y; As[nx][lcol+6][lrow]=ra1.z; As[nx][lcol+7][lrow]=ra1.w;
            Bs[nx][lcol+0][lrow]=rb0.x; Bs[nx][lcol+1][lrow]=rb0.y; Bs[nx][lcol+2][lrow]=rb0.z; Bs[nx][lcol+3][lrow]=rb0.w;
            Bs[nx][lcol+4][lrow]=rb1.x; Bs[nx][lcol+5][lrow]=rb1.y; Bs[nx][lcol+6][lrow]=rb1.z; Bs[nx][lcol+7][lrow]=rb1.w;
        }
        __syncthreads();
    }
    #pragma unroll
    for (int i=0;i<8;i++){
        int m = m0+ty*8+i;
        if (m >= M) continue;
        int n = n0+tx*8;
        if (n < N){
            *(float4*)(C+(long)m*ldc+n)   = make_float4(acc[i][0]*alpha,acc[i][1]*alpha,acc[i][2]*alpha,acc[i][3]*alpha);
            *(float4*)(C+(long)m*ldc+n+4) = make_float4(acc[i][4]*alpha,acc[i][5]*alpha,acc[i][6]*alpha,acc[i][7]*alpha);
        }
    }
}

__global__ __launch_bounds__(256, 2) void gemm_nt_k(
    const float* __restrict__ A, long sa, int lda,
    const float* __restrict__ B, long sb, int ldb,
    float* __restrict__ C, long sc, int ldc,
    int M, int N, int K, float alpha, int causal)
{
    int n0 = blockIdx.x*128, m0 = blockIdx.y*128;
    if (causal && n0 > m0+127) return;
    gemm_core(A + (long)blockIdx.z*sa, lda, B + (long)blockIdx.z*sb, ldb,
              C + (long)blockIdx.z*sc, ldc, M, N, K, alpha, m0, n0);
}

// fused qr+ki+wts (shared A=hidden, K=2048): tiles 0-11 -> qr, 12 -> ki, 13 -> wts
__global__ __launch_bounds__(256, 2) void gemm_qr_fused_k(
    const float* __restrict__ hidden,
    const float* __restrict__ wq_a, float* __restrict__ qr,
    const float* __restrict__ idx_wk, float* __restrict__ ki,
    const float* __restrict__ idx_wproj, float* __restrict__ wts, float alpha2)
{
    int bx = blockIdx.x, m0 = blockIdx.y*128;
    if (bx < 12)      gemm_core(hidden, DMM, wq_a, DMM, qr, QRR, SQ, QRR, DMM, 1.f, m0, bx*128);
    else if (bx == 12) gemm_core(hidden, DMM, idx_wk, DMM, ki, 128, SQ, 128, DMM, 1.f, m0, 0);
    else               gemm_core(hidden, DMM, idx_wproj, DMM, wts, 32, SQ, 32, DMM, alpha2, m0, 0);
}

// ---------------- cvt / norms / ropes ----------------
__global__ void cvt_hilo_k(const float* __restrict__ in, bf16* __restrict__ hi, bf16* __restrict__ lo, int n){
    int i = blockIdx.x*256 + threadIdx.x;
    if (i < n){
        float x = in[i]; bf16 h = __float2bfloat16(x);
        hi[i] = h; lo[i] = __float2bfloat16(x - __bfloat162float(h));
    }
}
__global__ void rmsnorm_k(const float* __restrict__ in, int ldi,
                          float* __restrict__ out, int ldo,
                          const float* __restrict__ w, int D){
    int s = blockIdx.x, tid = threadIdx.x;
    __shared__ float red[256];
    const float* ip = in + (long)s*ldi;
    float ss = 0.f;
    for (int d=tid; d<D; d+=256){ float v = ip[d]; ss += v*v; }
    red[tid]=ss; __syncthreads();
    for (int o=128;o>0;o>>=1){ if(tid<o) red[tid]+=red[tid+o]; __syncthreads(); }
    float scale = rsqrtf(red[0]/(float)D + 1e-6f);
    float* op = out + (long)s*ldo;
    for (int d=tid; d<D; d+=256) op[d] = ip[d]*scale*w[d];
}
__global__ void rope_q_k(float* __restrict__ q, const float* __restrict__ cs, const float* __restrict__ sn){
    int s = blockIdx.x, tid = threadIdx.x, h = tid>>5, i = tid&31;
    float c = cs[s*32+i], si = sn[s*32+i];
    float* p = q + (long)s*3072 + h*192 + 128 + 2*i;
    float x0=p[0], x1=p[1]; p[0]=x0*c-x1*si; p[1]=x0*si+x1*c;
}
__global__ void build_k_k(const float* __restrict__ kvp, const float* __restrict__ kvall,
                          float* __restrict__ kk, const float* __restrict__ cs, const float* __restrict__ sn){
    int s = blockIdx.x, h = blockIdx.y, tid = threadIdx.x;
    float* dst = kk + ((long)s*16+h)*192;
    dst[tid] = kvp[(long)s*4096 + h*256 + tid];
    if (tid < 32){
        float c = cs[s*32+tid], si = sn[s*32+tid];
        float x0 = kvall[(long)s*576+512+2*tid], x1 = kvall[(long)s*576+513+2*tid];
        dst[128+2*tid]=x0*c-x1*si; dst[129+2*tid]=x0*si+x1*c;
    }
}
__global__ void rope_qi_k(float* __restrict__ qi, const float* __restrict__ cs, const float* __restrict__ sn){
    int s = blockIdx.x, tid = threadIdx.x, h = tid>>5, d = tid&31;
    float c = cs[s*32+d], si = sn[s*32+d];
    float* p = qi + (long)s*4096 + h*128;
    float x0=p[d], x1=p[d+32]; p[d]=x0*c-x1*si; p[d+32]=x0*si+x1*c;
}
__global__ void ln_rope_ki_k(float* __restrict__ ki, const float* __restrict__ w, const float* __restrict__ b,
                             const float* __restrict__ cs, const float* __restrict__ sn){
    int s = blockIdx.x, tid = threadIdx.x;
    __shared__ float red[128]; __shared__ float buf[128];
    float v = ki[(long)s*128+tid];
    red[tid]=v; __syncthreads();
    for (int o=64;o>0;o>>=1){ if(tid<o) red[tid]+=red[tid+o]; __syncthreads(); }
    float mean = red[0]/128.f; __syncthreads();
    float d = v-mean; red[tid]=d*d; __syncthreads();
    for (int o=64;o>0;o>>=1){ if(tid<o) red[tid]+=red[tid+o]; __syncthreads(); }
    float nv = d*rsqrtf(red[0]/128.f + 1e-5f)*w[tid] + b[tid];
    buf[tid]=nv; __syncthreads();
    float out;
    if (tid<32){ float c=cs[s*32+tid], si=sn[s*32+tid]; out = buf[tid]*c - buf[tid+32]*si; }
    else if (tid<64){ int i=tid-32; float c=cs[s*32+i], si=sn[s*32+i]; out = buf[i]*si + buf[i+32]*c; }
    else out = nv;
    ki[(long)s*128+tid] = out;
}
// ---------------- indexer (fp32 SIMT, baseline-identical chains) -----------
__global__ __launch_bounds__(256, 2) void indexer_k(
    const float* __restrict__ qi, const float* __restrict__ ki,
    const float* __restrict__ wts, float* __restrict__ out){
    int t0 = blockIdx.x*64, s0 = blockIdx.y*128;
    if (t0 > s0+127) return;
    __shared__ float Bs[128][64]; __shared__ float As[16][128]; __shared__ float Ws[128][16];
    int tx = threadIdx.x, ty = threadIdx.y, tid = ty*16+tx;
    {
        int t = tid>>2, kb = (tid&3)*32;
        const float* kp = ki + (long)(t0+t)*128 + kb;
        #pragma unroll
        for (int c=0; c<32; c+=4){
            float4 v = *(const float4*)(kp+c);
            Bs[kb+c][t]=v.x; Bs[kb+c+1][t]=v.y; Bs[kb+c+2][t]=v.z; Bs[kb+c+3][t]=v.w;
        }
    }
    const float scl = 0.08838834764831845f;
    float fin[8][4] = {};
    int arow = tid>>1, acol = (tid&1)*8;
    for (int hg=0; hg<2; hg++){
        __syncthreads();
        for (int i=tid; i<2048; i+=256)
            Ws[i>>4][i&15] = wts[(long)(s0+(i>>4))*32 + hg*16 + (i&15)];
        __syncthreads();
        for (int hh=0; hh<16; hh++){
            int h = hg*16+hh;
            float acc[8][4] = {};
            #pragma unroll
            for (int kc=0; kc<8; kc++){
                const float* qp = qi + (long)(s0+arow)*4096 + h*128 + kc*16 + acol;
                float4 v0 = *(const float4*)(qp), v1 = *(const float4*)(qp+4);
                __syncthreads();
                As[acol+0][arow]=v0.x; As[acol+1][arow]=v0.y; As[acol+2][arow]=v0.z; As[acol+3][arow]=v0.w;
                As[acol+4][arow]=v1.x; As[acol+5][arow]=v1.y; As[acol+6][arow]=v1.z; As[acol+7][arow]=v1.w;
                __syncthreads();
                #pragma unroll
                for (int k=0; k<16; k++){
                    float4 a0 = *(const float4*)(&As[k][ty*8]);
                    float4 a1 = *(const float4*)(&As[k][ty*8+4]);
                    float4 b4 = *(const float4*)(&Bs[kc*16+k][tx*4]);
                    float a[8]={a0.x,a0.y,a0.z,a0.w,a1.x,a1.y,a1.z,a1.w};
                    float b[4]={b4.x,b4.y,b4.z,b4.w};
                    #pragma unroll
                    for (int i=0;i<8;i++)
                        #pragma unroll
                        for (int j=0;j<4;j++) acc[i][j]+=a[i]*b[j];
                }
            }
            #pragma unroll
            for (int i=0;i<8;i++){
                float wv = Ws[ty*8+i][hh];
                #pragma unroll
                for (int j=0;j<4;j++) fin[i][j]+=fmaxf(acc[i][j]*scl,0.f)*wv;
            }
        }
    }
    #pragma unroll
    for (int i=0;i<8;i++){
        float4 o = make_float4(fin[i][0],fin[i][1],fin[i][2],fin[i][3]);
        *(float4*)(out + (long)(s0+ty*8+i)*SQ + t0 + tx*4) = o;
    }
}
// ---------------- top-512 via exact radix-select (comb bit-identical) ------
__device__ __forceinline__ uint32_t fmap(float f){
    uint32_t u = __float_as_uint(f);
    return (u & 0x80000000u) ? ~u : (u | 0x80000000u);
}
__global__ __launch_bounds__(256) void topk_mask_k(const float* __restrict__ iscore, float* __restrict__ comb){
    int s = blockIdx.x, tid = threadIdx.x;
    __shared__ float xo[2048];
    __shared__ unsigned char sel[2048];
    __shared__ int hist[256];
    __shared__ int sh_b, sh_K, s_cnt;
    for (int t=tid; t<2048; t+=256){
        xo[t] = (t<=s) ? iscore[(long)s*SQ+t] : NEG_INF;
        sel[t] = 0;
    }
    if (tid==0){ s_cnt=0; sh_K=TOPK; }
    __syncthreads();
    if (s <= TOPK-1){
        for (int t=tid; t<2048; t+=256) comb[(long)s*SQ+t] = (t<=s)?0.f:NEG_INF;
        return;
    }
    uint32_t prefix = 0;
    for (int pass=0; pass<4; pass++){
        int shift = 24 - 8*pass;
        uint32_t maskHi = (pass==0) ? 0u : (0xFFFFFFFFu << (shift+8));
        hist[tid & 255] = 0;
        __syncthreads();
        for (int t=tid; t<=s; t+=256){
            uint32_t u = fmap(xo[t]);
            if ((u & maskHi) == prefix)
                atomicAdd(&hist[(u >> shift) & 255], 1);
        }
        __syncthreads();
        if (tid==0){
            int K = sh_K, cum = 0, b = 255;
            for (; b>=0; b--){
                int c = hist[b];
                if (cum + c >= K){ sh_b = b; sh_K = K - cum; break; }
                cum += c;
            }
        }
        __syncthreads();
        prefix |= ((uint32_t)sh_b) << shift;
        __syncthreads();
    }
    uint32_t mT = prefix;
    float T = (mT & 0x80000000u) ? __uint_as_float(mT ^ 0x80000000u) : __uint_as_float(~mT);
    int local = 0;
    for (int t=tid; t<=s; t+=256)
        if (xo[t] > T){ sel[t] = 1; local++; }
    atomicAdd(&s_cnt, local);
    __syncthreads();
    if (tid==0){
        int quota = TOPK - s_cnt;
        for (int t=0; t<=s && quota>0; t++)
            if (!sel[t] && xo[t] == T){ sel[t]=1; quota--; }
    }
    __syncthreads();
    for (int t=tid; t<2048; t+=256)
        comb[(long)s*SQ+t] = sel[t] ? 0.f : NEG_INF;
}
// ---------------- masked softmax -> bf16 hi/lo probs, range-limited --------
__global__ void softmax2_k(const float* __restrict__ scores, const float* __restrict__ comb,
                           bf16* __restrict__ phi, bf16* __restrict__ plo){
    int s = blockIdx.x, h = blockIdx.y, tid = threadIdx.x;
    long ro = ((long)h*SQ+s)*SQ;
    const float* row = scores + ro;
    const float* cm = comb + (long)s*SQ;
    int lim = ((s>>7)+1)<<7;
    __shared__ float red[256];
    float m = NEG_INF;
    for (int t=tid;t<lim;t+=256) if (cm[t]==0.f) m = fmaxf(m, row[t]);
    red[tid]=m; __syncthreads();
    for (int o=128;o>0;o>>=1){ if(tid<o) red[tid]=fmaxf(red[tid],red[tid+o]); __syncthreads(); }
    m = red[0]; __syncthreads();
    float sum=0.f;
    for (int t=tid;t<lim;t+=256)
        if (cm[t]==0.f) sum += expf(row[t]-m);
    red[tid]=sum; __syncthreads();
    for (int o=128;o>0;o>>=1){ if(tid<o) red[tid]+=red[tid+o]; __syncthreads(); }
    float inv = 1.f/red[0];
    for (int t=tid;t<lim;t+=256){
        float p = (cm[t]==0.f) ? expf(row[t]-m)*inv : 0.f;
        bf16 hb = __float2bfloat16(p);
        phi[ro+t] = hb;
        plo[ro+t] = __float2bfloat16(p - __bfloat162float(hb));
    }
}
// ---------------- v^T build: kvp -> vT[h][n][k] bf16 hi/lo -----------------
__global__ void build_vT_k(const float* __restrict__ kvp, bf16* __restrict__ vhi, bf16* __restrict__ vlo){
    int s = blockIdx.x*256 + threadIdx.x;
    int n = blockIdx.y, h = blockIdx.z;
    float v = kvp[(long)s*4096 + h*256 + 128 + n];
    long o = ((long)h*128 + n)*2048 + s;
    bf16 hb = __float2bfloat16(v);
    vhi[o] = hb; vlo[o] = __float2bfloat16(v - __bfloat162float(hb));
}

// ================= host =================
static void cvtS(cudaStream_t st, const float* in, bf16* hi, bf16* lo, int n){
    cvt_hilo_k<<<(n+255)/256, 256, 0, st>>>(in, hi, lo, n);
}
#define GSYM(p, s) cudaGetSymbolAddress((void**)&p, s)

extern "C" void kernel_launch(void* const* d_in, const int* in_sizes, int n_in,
                              void* d_out, int out_size)
{
    if (n_in < 16) return;
    const float *hidden,*wq_a,*q_norm_w,*wq_b,*wkv_a,*kv_norm_w,*wkv_b,*wo;
    const float *idx_wq_b,*idx_wk,*idx_kn_w,*idx_kn_b,*idx_wproj,*fcos,*fsin;
    if (in_sizes[1] == 1536*2048){
        hidden=(const float*)d_in[0];  wq_a=(const float*)d_in[1];
        q_norm_w=(const float*)d_in[2]; wq_b=(const float*)d_in[3];
        wkv_a=(const float*)d_in[4];   kv_norm_w=(const float*)d_in[5];
        wkv_b=(const float*)d_in[6];   wo=(const float*)d_in[7];
        idx_wq_b=(const float*)d_in[8]; idx_wk=(const float*)d_in[9];
        idx_kn_w=(const float*)d_in[10]; idx_kn_b=(const float*)d_in[11];
        idx_wproj=(const float*)d_in[12]; fcos=(const float*)d_in[13]; fsin=(const float*)d_in[14];
    } else {
        hidden=(const float*)d_in[0]; fcos=(const float*)d_in[1]; fsin=(const float*)d_in[2];
        wq_a=(const float*)d_in[4];   q_norm_w=(const float*)d_in[5];
        wq_b=(const float*)d_in[6];   wkv_a=(const float*)d_in[7];
        kv_norm_w=(const float*)d_in[8]; wkv_b=(const float*)d_in[9];
        wo=(const float*)d_in[10];    idx_wq_b=(const float*)d_in[11];
        idx_wk=(const float*)d_in[12]; idx_kn_w=(const float*)d_in[13];
        idx_kn_b=(const float*)d_in[14]; idx_wproj=(const float*)d_in[15];
    }

    float *qr,*q,*kvall,*kv,*kvp,*k,*qi,*ki,*wts,*iscore,*comb,*scores,*attnout;
    GSYM(qr,g_qr); GSYM(q,g_q); GSYM(kvall,g_kvall); GSYM(kv,g_kv); GSYM(kvp,g_kvp); GSYM(k,g_k);
    GSYM(qi,g_qi); GSYM(ki,g_ki); GSYM(wts,g_wts); GSYM(iscore,g_iscore);
    GSYM(comb,g_comb); GSYM(scores,g_scores); GSYM(attnout,g_attnout);
    bf16 *h_hi,*h_lo,*wqb_hi,*wqb_lo,*wkva_hi,*wkva_lo,*wkvb_hi,*wkvb_lo,*wo_hi,*wo_lo;
    bf16 *qrn_hi,*qrn_lo,*kvn_hi,*kvn_lo,*qh_hi,*qh_lo,*kh_hi,*kh_lo,*at_hi,*at_lo;
    bf16 *p_hi,*p_lo,*vT_hi,*vT_lo;
    GSYM(h_hi,g_h_hi); GSYM(h_lo,g_h_lo);
    GSYM(wqb_hi,g_wqb_hi); GSYM(wqb_lo,g_wqb_lo); GSYM(wkva_hi,g_wkva_hi); GSYM(wkva_lo,g_wkva_lo);
    GSYM(wkvb_hi,g_wkvb_hi); GSYM(wkvb_lo,g_wkvb_lo); GSYM(wo_hi,g_wo_hi); GSYM(wo_lo,g_wo_lo);
    GSYM(qrn_hi,g_qrn_hi); GSYM(qrn_lo,g_qrn_lo); GSYM(kvn_hi,g_kvn_hi); GSYM(kvn_lo,g_kvn_lo);
    GSYM(qh_hi,g_qh_hi); GSYM(qh_lo,g_qh_lo); GSYM(kh_hi,g_kh_hi); GSYM(kh_lo,g_kh_lo);
    GSYM(at_hi,g_at_hi); GSYM(at_lo,g_at_lo);
    GSYM(p_hi,g_p_hi); GSYM(p_lo,g_p_lo); GSYM(vT_hi,g_vT_hi); GSYM(vT_lo,g_vT_lo);
    float* outp = (float*)d_out;

    static cudaStream_t sB = 0;
    static cudaEvent_t evStart = 0, evQr = 0, evB = 0;
    if (!sB){
        cudaStreamCreateWithFlags(&sB, cudaStreamNonBlocking);
        cudaEventCreateWithFlags(&evStart, cudaEventDisableTiming);
        cudaEventCreateWithFlags(&evQr, cudaEventDisableTiming);
        cudaEventCreateWithFlags(&evB, cudaEventDisableTiming);
        cudaFuncSetAttribute(gemm_mma_nt, cudaFuncAttributeMaxDynamicSharedMemorySize, MMA_SMEM);
    }

    dim3 blk(16,16);
    const float inv_sqrt192 = 0.07216878364870323f;
    const float inv_sqrt32  = 0.17677669529663687f;

    // ---- fork ----
    cudaEventRecord(evStart, 0);
    cudaStreamWaitEvent(sB, evStart, 0);

    // ---- stream B (smooth path, part 1: independent of qr) ----
    cvtS(sB, hidden,h_hi,h_lo,2048*2048);
    cvtS(sB, wkv_a,wkva_hi,wkva_lo,576*2048);
    cvtS(sB, wq_b,wqb_hi,wqb_lo,3072*1536);
    cvtS(sB, wkv_b,wkvb_hi,wkvb_lo,4096*512);
    cvtS(sB, wo,wo_hi,wo_lo,2048*2048);
    gemm_mma_nt<<<dim3(5,16,1),256,MMA_SMEM,sB>>>(h_hi,h_lo,0,2048, wkva_hi,wkva_lo,0,2048, kvall,0,576, 576,2048,1.f,0);
    rmsnorm_k<<<SQ,256,0,sB>>>(kvall,576, kv,KRR, kv_norm_w,KRR);
    cvtS(sB, kv,kvn_hi,kvn_lo,2048*512);
    gemm_mma_nt<<<dim3(32,16,1),256,MMA_SMEM,sB>>>(kvn_hi,kvn_lo,0,512, wkvb_hi,wkvb_lo,0,512, kvp,0,4096, 4096,512,1.f,0);
    build_k_k<<<dim3(SQ,NH),128,0,sB>>>(kvp,kvall,k,fcos,fsin);
    build_vT_k<<<dim3(8,128,16),256,0,sB>>>(kvp, vT_hi, vT_lo);
    cvtS(sB, k,kh_hi,kh_lo,2048*3072);

    // ---- stream A (default): indexer-critical chain, EXACT fp32 baseline --
    gemm_qr_fused_k<<<dim3(14,16),blk>>>(hidden, wq_a, qr, idx_wk, ki, idx_wproj, wts, inv_sqrt32);
    rmsnorm_k<<<SQ,256>>>(qr,QRR, qr,QRR, q_norm_w,QRR);
    cudaEventRecord(evQr, 0);

    // ---- stream B (part 2: needs normed qr) ----
    cudaStreamWaitEvent(sB, evQr, 0);
    cvtS(sB, qr,qrn_hi,qrn_lo,2048*1536);
    gemm_mma_nt<<<dim3(24,16,1),256,MMA_SMEM,sB>>>(qrn_hi,qrn_lo,0,1536, wqb_hi,wqb_lo,0,1536, q,0,3072, 3072,1536,1.f,0);
    rope_q_k<<<SQ,512,0,sB>>>(q,fcos,fsin);
    cvtS(sB, q,qh_hi,qh_lo,2048*3072);
    gemm_mma_nt<<<dim3(16,16,16),256,MMA_SMEM,sB>>>(qh_hi,qh_lo,192,3072, kh_hi,kh_lo,192,3072,
                                                    scores,(long)SQ*SQ,SQ, SQ,192,inv_sqrt192,1);
    cudaEventRecord(evB, sB);

    // ---- stream A continues: qi -> indexer -> topk ----
    gemm_nt_k<<<dim3(32,16,1),blk>>>(qr,0,QRR, idx_wq_b,0,QRR, qi,0,4096, SQ,4096,QRR,1.f,0);
    rope_qi_k<<<SQ,1024>>>(qi,fcos,fsin);
    ln_rope_ki_k<<<SQ,128>>>(ki,idx_kn_w,idx_kn_b,fcos,fsin);
    indexer_k<<<dim3(SQ/64,SQ/128),blk>>>(qi,ki,wts,iscore);
    topk_mask_k<<<SQ,256>>>(iscore,comb);

    // ---- join + tail on default stream ----
    cudaStreamWaitEvent(0, evB, 0);
    softmax2_k<<<dim3(SQ,NH),256>>>(scores,comb,p_hi,p_lo);
    gemm_mma_nt<<<dim3(1,16,16),256,MMA_SMEM>>>(p_hi,p_lo,(long)SQ*SQ,SQ, vT_hi,vT_lo,(long)128*2048,2048,
                                                attnout,128,2048, 128,2048,1.f,2);
    cvtS(0, attnout,at_hi,at_lo,2048*2048);
    gemm_mma_nt<<<dim3(16,16,1),256,MMA_SMEM>>>(at_hi,at_lo,0,2048, wo_hi,wo_lo,0,2048, outp,0,2048, 2048,2048,1.f,0);
}